// round 2
// baseline (speedup 1.0000x reference)
#include <cuda_runtime.h>
#include <cuda_bf16.h>
#include <cstdint>

// Problem constants
constexpr int Bc = 2;
constexpr int Sc = 2048;
constexpr int Dc = 1024;
constexpr int Hc = 16;
constexpr int DKc = 64;
constexpr int Mc = Bc * Sc;  // 4096

// Scratch (device globals: allocation-free)
__device__ float g_Qh[(size_t)Bc * Hc * Sc * DKc];
__device__ float g_Kh[(size_t)Bc * Hc * Sc * DKc];
__device__ float g_Vh[(size_t)Bc * Hc * Sc * DKc];
__device__ float g_att[(size_t)Mc * Dc];

// ---------------------------------------------------------------------------
// Projection GEMM: out[m,n] = sum_k A[m,k] * W[n,k] + bias[n]
// A: [M=4096, K=1024] row-major, W: [N=1024, K=1024] row-major (A @ W^T).
// 128x128 block tile, BK=8, 8x8 per-thread microtile, 256 threads.
// HEAD=true  -> write to [B,H,S,DK] layout
// HEAD=false -> write to [M,N] row-major
// ---------------------------------------------------------------------------
template <bool HEAD>
__global__ void __launch_bounds__(256) proj_kernel(const float* __restrict__ A,
                                                   const float* __restrict__ W,
                                                   const float* __restrict__ bias,
                                                   float* __restrict__ out) {
    constexpr int BM = 128, BN = 128, BK = 8;
    __shared__ float As[BK][BM];
    __shared__ float Ws[BK][BN];

    const int tid = threadIdx.x;
    const int tx = tid & 15;        // 0..15 -> 8 cols each
    const int ty = tid >> 4;        // 0..15 -> 8 rows each
    const int row0 = blockIdx.y * BM;
    const int col0 = blockIdx.x * BN;

    // load mapping: 128 rows x 8 cols = 1024 floats, 256 threads * float4
    const int lr = tid >> 1;          // 0..127
    const int lc = (tid & 1) << 2;    // 0 or 4

    float acc[8][8] = {};

    const float* Ap = A + (size_t)row0 * Dc;
    const float* Wp = W + (size_t)col0 * Dc;

    for (int k0 = 0; k0 < Dc; k0 += BK) {
        float4 a4 = *reinterpret_cast<const float4*>(Ap + (size_t)lr * Dc + k0 + lc);
        float4 w4 = *reinterpret_cast<const float4*>(Wp + (size_t)lr * Dc + k0 + lc);
        As[lc + 0][lr] = a4.x; As[lc + 1][lr] = a4.y;
        As[lc + 2][lr] = a4.z; As[lc + 3][lr] = a4.w;
        Ws[lc + 0][lr] = w4.x; Ws[lc + 1][lr] = w4.y;
        Ws[lc + 2][lr] = w4.z; Ws[lc + 3][lr] = w4.w;
        __syncthreads();

#pragma unroll
        for (int k = 0; k < BK; k++) {
            float rm[8], rn[8];
#pragma unroll
            for (int i = 0; i < 8; i++) rm[i] = As[k][ty * 8 + i];
#pragma unroll
            for (int j = 0; j < 8; j++) rn[j] = Ws[k][tx * 8 + j];
#pragma unroll
            for (int i = 0; i < 8; i++)
#pragma unroll
                for (int j = 0; j < 8; j++) acc[i][j] += rm[i] * rn[j];
        }
        __syncthreads();
    }

#pragma unroll
    for (int i = 0; i < 8; i++) {
        const int m = row0 + ty * 8 + i;
        const int b = m >> 11;        // /2048
        const int s = m & 2047;
#pragma unroll
        for (int j = 0; j < 8; j++) {
            const int n = col0 + tx * 8 + j;
            const float val = acc[i][j] + bias[n];
            if (HEAD) {
                const int h = n >> 6, dk = n & 63;
                g_dummy_noop:;
                out[((size_t)((b * Hc + h) * Sc + s) << 6) + dk] = val;
            } else {
                out[(size_t)m * Dc + n] = val;
            }
        }
    }
}

// ---------------------------------------------------------------------------
// Flash attention (causal), fp32 SIMT.
// grid: (32 q-tiles, 32 b*h), 256 threads. 64x64 q/k tiles, DK=64.
// Dynamic smem: Qs[64][64], KsT[64][65], Vs[64][64], Ps[64][65], m/l/alpha[64]
// ---------------------------------------------------------------------------
constexpr int ATTN_SMEM_FLOATS = 64 * 64 + 64 * 65 + 64 * 64 + 64 * 65 + 3 * 64;
constexpr int ATTN_SMEM_BYTES = ATTN_SMEM_FLOATS * 4;  // 66816

__global__ void __launch_bounds__(256) attn_kernel(const float* __restrict__ Qh,
                                                   const float* __restrict__ Kh,
                                                   const float* __restrict__ Vh,
                                                   float* __restrict__ O) {
    extern __shared__ float sm[];
    float* Qs  = sm;                 // [64][64]
    float* KsT = Qs + 64 * 64;       // [64(d)][65(c)]
    float* Vs  = KsT + 64 * 65;      // [64(k)][64(dk)]
    float* Ps  = Vs + 64 * 64;       // [64(q)][65(k)]
    float* msm = Ps + 64 * 65;       // [64]
    float* lsm = msm + 64;           // [64]
    float* alf = lsm + 64;           // [64]

    const int tid = threadIdx.x;
    const int tx = tid & 15;   // col group (4 cols)
    const int ty = tid >> 4;   // row group (4 rows)
    const int qt = blockIdx.x;
    const int bh = blockIdx.y;

    const float* Qbase = Qh + ((size_t)bh * Sc + qt * 64) * DKc;
    const float* Kbase = Kh + (size_t)bh * Sc * DKc;
    const float* Vbase = Vh + (size_t)bh * Sc * DKc;

    // Load Q tile (row-major, same layout)
    for (int i = tid * 4; i < 64 * 64; i += 1024) {
        *reinterpret_cast<float4*>(Qs + i) =
            *reinterpret_cast<const float4*>(Qbase + i);
    }
    if (tid < 64) { msm[tid] = -1e30f; lsm[tid] = 0.0f; }

    float Oacc[4][4] = {};
    const float scale = 0.125f;  // 1/sqrt(64)

    __syncthreads();

    for (int kt = 0; kt <= qt; ++kt) {
        const float* Kb = Kbase + (size_t)kt * 64 * DKc;
        const float* Vb = Vbase + (size_t)kt * 64 * DKc;
        // Load K (transposed into KsT[d][c]) and V
        for (int i = tid * 4; i < 64 * 64; i += 1024) {
            const int c = i >> 6, d = i & 63;
            float4 k4 = *reinterpret_cast<const float4*>(Kb + i);
            KsT[(d + 0) * 65 + c] = k4.x;
            KsT[(d + 1) * 65 + c] = k4.y;
            KsT[(d + 2) * 65 + c] = k4.z;
            KsT[(d + 3) * 65 + c] = k4.w;
            *reinterpret_cast<float4*>(Vs + i) =
                *reinterpret_cast<const float4*>(Vb + i);
        }
        __syncthreads();

        // S = Q @ K^T (4x4 per thread over d=0..63)
        float sacc[4][4] = {};
#pragma unroll 8
        for (int d = 0; d < 64; d++) {
            float qv[4], kv[4];
#pragma unroll
            for (int i = 0; i < 4; i++) qv[i] = Qs[(ty * 4 + i) * 64 + d];
#pragma unroll
            for (int j = 0; j < 4; j++) kv[j] = KsT[d * 65 + tx * 4 + j];
#pragma unroll
            for (int i = 0; i < 4; i++)
#pragma unroll
                for (int j = 0; j < 4; j++) sacc[i][j] += qv[i] * kv[j];
        }

        // scale + causal mask + store to Ps
        const bool diag = (kt == qt);
#pragma unroll
        for (int i = 0; i < 4; i++) {
            const int r = ty * 4 + i;
#pragma unroll
            for (int j = 0; j < 4; j++) {
                const int c = tx * 4 + j;
                float v = sacc[i][j] * scale;
                if (diag && c > r) v = -1e30f;
                Ps[r * 65 + c] = v;
            }
        }
        __syncthreads();

        // Online softmax: 4 threads per row, 16 cols each
        {
            const int row = tid >> 2;
            const int part = tid & 3;
            float* prow = Ps + row * 65 + part * 16;
            float mx = -1e30f;
#pragma unroll
            for (int c = 0; c < 16; c++) mx = fmaxf(mx, prow[c]);
            mx = fmaxf(mx, __shfl_xor_sync(0xffffffffu, mx, 1));
            mx = fmaxf(mx, __shfl_xor_sync(0xffffffffu, mx, 2));
            const float mold = msm[row];
            const float mnew = fmaxf(mold, mx);
            const float alpha = __expf(mold - mnew);
            float ssum = 0.0f;
#pragma unroll
            for (int c = 0; c < 16; c++) {
                const float p = __expf(prow[c] - mnew);
                prow[c] = p;
                ssum += p;
            }
            ssum += __shfl_xor_sync(0xffffffffu, ssum, 1);
            ssum += __shfl_xor_sync(0xffffffffu, ssum, 2);
            if (part == 0) {
                msm[row] = mnew;
                alf[row] = alpha;
                lsm[row] = lsm[row] * alpha + ssum;
            }
        }
        __syncthreads();

        // O = O*alpha + P @ V
        {
            float al[4];
#pragma unroll
            for (int i = 0; i < 4; i++) al[i] = alf[ty * 4 + i];
#pragma unroll
            for (int i = 0; i < 4; i++)
#pragma unroll
                for (int j = 0; j < 4; j++) Oacc[i][j] *= al[i];
#pragma unroll 8
            for (int kk = 0; kk < 64; kk++) {
                float pv[4];
#pragma unroll
                for (int i = 0; i < 4; i++) pv[i] = Ps[(ty * 4 + i) * 65 + kk];
                const float4 v4 = *reinterpret_cast<const float4*>(Vs + kk * 64 + tx * 4);
                const float vv[4] = {v4.x, v4.y, v4.z, v4.w};
#pragma unroll
                for (int i = 0; i < 4; i++)
#pragma unroll
                    for (int j = 0; j < 4; j++) Oacc[i][j] += pv[i] * vv[j];
            }
        }
        __syncthreads();
    }

    // Normalize and write to g_att in [B,S,D] layout (n = h*64+dk)
    const int b = bh >> 4;
    const int h = bh & 15;
#pragma unroll
    for (int i = 0; i < 4; i++) {
        const int r = ty * 4 + i;
        const float inv = 1.0f / lsm[r];
        const int s = qt * 64 + r;
        float* orow = O + ((size_t)(b * Sc + s)) * Dc + h * 64 + tx * 4;
        float4 o4;
        o4.x = Oacc[i][0] * inv;
        o4.y = Oacc[i][1] * inv;
        o4.z = Oacc[i][2] * inv;
        o4.w = Oacc[i][3] * inv;
        *reinterpret_cast<float4*>(orow) = o4;
    }
}

// ---------------------------------------------------------------------------
extern "C" void kernel_launch(void* const* d_in, const int* in_sizes, int n_in,
                              void* d_out, int out_size) {
    const float* q  = (const float*)d_in[0];
    const float* k  = (const float*)d_in[1];
    const float* v  = (const float*)d_in[2];
    // d_in[3] = mask (causal implemented directly)
    const float* Wq = (const float*)d_in[4];
    const float* bq = (const float*)d_in[5];
    const float* Wk = (const float*)d_in[6];
    const float* bk = (const float*)d_in[7];
    const float* Wv = (const float*)d_in[8];
    const float* bv = (const float*)d_in[9];
    const float* Wo = (const float*)d_in[10];
    const float* bo = (const float*)d_in[11];
    float* out = (float*)d_out;

    float *Qh, *Kh, *Vh, *Att;
    cudaGetSymbolAddress((void**)&Qh, g_Qh);
    cudaGetSymbolAddress((void**)&Kh, g_Kh);
    cudaGetSymbolAddress((void**)&Vh, g_Vh);
    cudaGetSymbolAddress((void**)&Att, g_att);

    cudaFuncSetAttribute(attn_kernel, cudaFuncAttributeMaxDynamicSharedMemorySize,
                         ATTN_SMEM_BYTES);

    dim3 pgrid(Dc / 128, Mc / 128);  // (8, 32)
    proj_kernel<true><<<pgrid, 256>>>(q, Wq, bq, Qh);
    proj_kernel<true><<<pgrid, 256>>>(k, Wk, bk, Kh);
    proj_kernel<true><<<pgrid, 256>>>(v, Wv, bv, Vh);

    dim3 agrid(Sc / 64, Bc * Hc);    // (32, 32)
    attn_kernel<<<agrid, 256, ATTN_SMEM_BYTES>>>(Qh, Kh, Vh, Att);

    proj_kernel<false><<<pgrid, 256>>>(Att, Wo, bo, out);
}

// round 4
// speedup vs baseline: 4.8853x; 4.8853x over previous
#include <cuda_runtime.h>
#include <cuda_bf16.h>
#include <cstdint>

// Problem constants
constexpr int Bc = 2;
constexpr int Sc = 2048;
constexpr int Dc = 1024;
constexpr int Hc = 16;
constexpr int DKc = 64;
constexpr int Mc = Bc * Sc;  // 4096

// Scratch (device globals: allocation-free)
__device__ float g_Qh[(size_t)Bc * Hc * Sc * DKc];
__device__ float g_Kh[(size_t)Bc * Hc * Sc * DKc];
__device__ float g_Vh[(size_t)Bc * Hc * Sc * DKc];
__device__ float g_att[(size_t)Mc * Dc];

// ---------------------------------------------------------------------------
// Helpers
// ---------------------------------------------------------------------------
__device__ __forceinline__ uint32_t smem_u32(const void* p) {
    uint32_t a;
    asm("{ .reg .u64 t; cvta.to.shared.u64 t, %1; cvt.u32.u64 %0, t; }"
        : "=r"(a) : "l"(p));
    return a;
}
__device__ __forceinline__ void cp_async16(uint32_t s, const void* g) {
    asm volatile("cp.async.cg.shared.global [%0], [%1], 16;" :: "r"(s), "l"(g));
}
__device__ __forceinline__ void cp_commit() {
    asm volatile("cp.async.commit_group;" ::: "memory");
}
template <int N>
__device__ __forceinline__ void cp_wait() {
    asm volatile("cp.async.wait_group %0;" :: "n"(N) : "memory");
}
__device__ __forceinline__ uint32_t f2tf32(float f) {
    uint32_t u;
    asm("cvt.rna.tf32.f32 %0, %1;" : "=r"(u) : "f"(f));
    return u;
}
__device__ __forceinline__ void mma_tf32(float* C, const uint32_t* A,
                                         const uint32_t* B) {
    asm volatile(
        "mma.sync.aligned.m16n8k8.row.col.f32.tf32.tf32.f32 "
        "{%0,%1,%2,%3}, {%4,%5,%6,%7}, {%8,%9}, {%0,%1,%2,%3};"
        : "+f"(C[0]), "+f"(C[1]), "+f"(C[2]), "+f"(C[3])
        : "r"(A[0]), "r"(A[1]), "r"(A[2]), "r"(A[3]), "r"(B[0]), "r"(B[1]));
}

// ---------------------------------------------------------------------------
// Projection GEMM (tf32 mma): out[m,n] = sum_k A[m,k]*W[n,k] + bias[n]
// 128x128x32 tiles, 256 threads / 8 warps (4x2), double-buffered cp.async.
// HEAD=true -> [B,H,S,DK] output layout; else row-major [M,N].
// ---------------------------------------------------------------------------
constexpr int PBK = 32;
constexpr int PSTR = PBK + 4;              // 36 floats, conflict-free frags
constexpr int PTILE = 128 * PSTR;          // floats per tile (4608)
constexpr int PROJ_SMEM = 4 * PTILE * 4;   // A0,B0,A1,B1 = 73728 B

template <bool HEAD>
__global__ void __launch_bounds__(256) proj_mma_kernel(const float* __restrict__ A,
                                                       const float* __restrict__ W,
                                                       const float* __restrict__ bias,
                                                       float* __restrict__ out) {
    extern __shared__ float sm[];
    const uint32_t smb = smem_u32(sm);

    const int tid = threadIdx.x;
    const int wid = tid >> 5;
    const int lid = tid & 31;
    const int g = lid >> 2;       // group 0..7
    const int t4 = lid & 3;       // 0..3
    const int wm = wid & 3;       // 4 warps along M (32 rows each)
    const int wn = wid >> 2;      // 2 warps along N (64 cols each)
    const int row0 = blockIdx.y * 128;
    const int col0 = blockIdx.x * 128;

    const float* Ap = A + (size_t)row0 * Dc;
    const float* Wp = W + (size_t)col0 * Dc;

    // gmem->smem: 1024 16B chunks per tile, 4 per thread per tile
    auto load_tiles = [&](int kb, int buf) {
        const int k0 = kb * PBK;
        const uint32_t abase = smb + (uint32_t)(buf * 2 * PTILE) * 4;
        const uint32_t bbase = abase + (uint32_t)PTILE * 4;
#pragma unroll
        for (int i = 0; i < 4; i++) {
            const int ch = tid + i * 256;
            const int r = ch >> 3;
            const int c = ch & 7;
            const uint32_t so = (uint32_t)(r * PSTR + c * 4) * 4;
            cp_async16(abase + so, Ap + (size_t)r * Dc + k0 + c * 4);
            cp_async16(bbase + so, Wp + (size_t)r * Dc + k0 + c * 4);
        }
        cp_commit();
    };

    float acc[2][8][4] = {};

    load_tiles(0, 0);
    const int NKB = Dc / PBK;  // 32
    for (int kb = 0; kb < NKB; kb++) {
        const int buf = kb & 1;
        if (kb + 1 < NKB) {
            load_tiles(kb + 1, buf ^ 1);
            cp_wait<1>();
        } else {
            cp_wait<0>();
        }
        __syncthreads();

        const float* a_s = sm + buf * 2 * PTILE;
        const float* b_s = a_s + PTILE;
#pragma unroll
        for (int ks = 0; ks < 4; ks++) {
            const int kk = ks * 8 + t4;
            uint32_t af[2][4];
#pragma unroll
            for (int mt = 0; mt < 2; mt++) {
                const int r = wm * 32 + mt * 16 + g;
                af[mt][0] = f2tf32(a_s[r * PSTR + kk]);
                af[mt][1] = f2tf32(a_s[(r + 8) * PSTR + kk]);
                af[mt][2] = f2tf32(a_s[r * PSTR + kk + 4]);
                af[mt][3] = f2tf32(a_s[(r + 8) * PSTR + kk + 4]);
            }
#pragma unroll
            for (int nt = 0; nt < 8; nt++) {
                const int n = wn * 64 + nt * 8 + g;
                uint32_t bf[2];
                bf[0] = f2tf32(b_s[n * PSTR + kk]);
                bf[1] = f2tf32(b_s[n * PSTR + kk + 4]);
#pragma unroll
                for (int mt = 0; mt < 2; mt++) mma_tf32(acc[mt][nt], af[mt], bf);
            }
        }
        __syncthreads();
    }

    // Epilogue
#pragma unroll
    for (int mt = 0; mt < 2; mt++) {
#pragma unroll
        for (int half = 0; half < 2; half++) {
            const int m = row0 + wm * 32 + mt * 16 + g + half * 8;
            const int b = m >> 11;
            const int s = m & 2047;
#pragma unroll
            for (int nt = 0; nt < 8; nt++) {
                const int n = col0 + wn * 64 + nt * 8 + t4 * 2;
                float2 o;
                o.x = acc[mt][nt][half * 2 + 0] + bias[n];
                o.y = acc[mt][nt][half * 2 + 1] + bias[n + 1];
                if (HEAD) {
                    const int h = n >> 6, dk = n & 63;
                    *reinterpret_cast<float2*>(
                        out + ((size_t)((b * Hc + h) * Sc + s) << 6) + dk) = o;
                } else {
                    *reinterpret_cast<float2*>(out + (size_t)m * Dc + n) = o;
                }
            }
        }
    }
}

// ---------------------------------------------------------------------------
// Flash attention (causal) with tf32 mma for QK^T and PV, fp32 softmax.
// 64x64 tiles, 256 threads / 8 warps (4x2: 16 q-rows x 32 cols per warp).
// ---------------------------------------------------------------------------
constexpr int AST = 68;  // padded row stride (floats)
constexpr int ATTN_SMEM_BYTES = (4 * 64 * AST + 3 * 64) * 4;  // 70400

__global__ void __launch_bounds__(256) attn_kernel(const float* __restrict__ Qh,
                                                   const float* __restrict__ Kh,
                                                   const float* __restrict__ Vh,
                                                   float* __restrict__ O) {
    extern __shared__ float smf[];
    float* Qs  = smf;                 // [64][AST] row-major (q, d)
    float* Ks  = Qs + 64 * AST;       // [64][AST] row-major (key, d)
    float* Vt  = Ks + 64 * AST;       // [64][AST] (d, key)
    float* Ps  = Vt + 64 * AST;       // [64][AST] (q, key)
    float* msm = Ps + 64 * AST;
    float* lsm = msm + 64;
    float* alf = lsm + 64;

    const int tid = threadIdx.x;
    const int wid = tid >> 5;
    const int lid = tid & 31;
    const int g = lid >> 2;
    const int t4 = lid & 3;
    const int wm = wid & 3;    // 16-row q slice
    const int wn = wid >> 2;   // 32-col slice
    const int qt = blockIdx.x;
    const int bh = blockIdx.y;

    const float* Qbase = Qh + ((size_t)bh * Sc + qt * 64) * DKc;
    const float* Kbase = Kh + (size_t)bh * Sc * DKc;
    const float* Vbase = Vh + (size_t)bh * Sc * DKc;

    // Load Q tile
    for (int i = tid * 4; i < 64 * 64; i += 1024) {
        const int r = i >> 6, c = i & 63;
        *reinterpret_cast<float4*>(Qs + r * AST + c) =
            *reinterpret_cast<const float4*>(Qbase + i);
    }
    if (tid < 64) { msm[tid] = -1e30f; lsm[tid] = 0.0f; }

    float Oacc[4][4] = {};
    const float scale = 0.125f;  // 1/sqrt(64)
    const int r0 = wm * 16 + g;
    const int r1 = r0 + 8;

    __syncthreads();

    for (int kt = 0; kt <= qt; ++kt) {
        const float* Kb = Kbase + (size_t)kt * 64 * DKc;
        const float* Vb = Vbase + (size_t)kt * 64 * DKc;
        for (int i = tid * 4; i < 64 * 64; i += 1024) {
            const int r = i >> 6, d = i & 63;
            *reinterpret_cast<float4*>(Ks + r * AST + d) =
                *reinterpret_cast<const float4*>(Kb + i);
            float4 v4 = *reinterpret_cast<const float4*>(Vb + i);
            Vt[(d + 0) * AST + r] = v4.x;
            Vt[(d + 1) * AST + r] = v4.y;
            Vt[(d + 2) * AST + r] = v4.z;
            Vt[(d + 3) * AST + r] = v4.w;
        }
        __syncthreads();

        // S = Q @ K^T via mma (k-dim = 64)
        float sacc[4][4] = {};
#pragma unroll
        for (int ks = 0; ks < 8; ks++) {
            const int kk = ks * 8 + t4;
            uint32_t af[4];
            af[0] = f2tf32(Qs[r0 * AST + kk]);
            af[1] = f2tf32(Qs[r1 * AST + kk]);
            af[2] = f2tf32(Qs[r0 * AST + kk + 4]);
            af[3] = f2tf32(Qs[r1 * AST + kk + 4]);
#pragma unroll
            for (int nt = 0; nt < 4; nt++) {
                const int n = wn * 32 + nt * 8 + g;
                uint32_t bf[2];
                bf[0] = f2tf32(Ks[n * AST + kk]);
                bf[1] = f2tf32(Ks[n * AST + kk + 4]);
                mma_tf32(sacc[nt], af, bf);
            }
        }

        // scale + causal mask + store S -> Ps
        const bool diag = (kt == qt);
#pragma unroll
        for (int nt = 0; nt < 4; nt++) {
            const int c = wn * 32 + nt * 8 + t4 * 2;
            float2 v0, v1;
            v0.x = sacc[nt][0] * scale;
            v0.y = sacc[nt][1] * scale;
            v1.x = sacc[nt][2] * scale;
            v1.y = sacc[nt][3] * scale;
            if (diag) {
                if (c > r0) v0.x = -1e30f;
                if (c + 1 > r0) v0.y = -1e30f;
                if (c > r1) v1.x = -1e30f;
                if (c + 1 > r1) v1.y = -1e30f;
            }
            *reinterpret_cast<float2*>(Ps + r0 * AST + c) = v0;
            *reinterpret_cast<float2*>(Ps + r1 * AST + c) = v1;
        }
        __syncthreads();

        // Online softmax: 4 threads per row, 16 cols each
        {
            const int row = tid >> 2;
            const int part = tid & 3;
            float* prow = Ps + row * AST + part * 16;
            float mx = -1e30f;
#pragma unroll
            for (int c = 0; c < 16; c++) mx = fmaxf(mx, prow[c]);
            mx = fmaxf(mx, __shfl_xor_sync(0xffffffffu, mx, 1));
            mx = fmaxf(mx, __shfl_xor_sync(0xffffffffu, mx, 2));
            const float mold = msm[row];
            const float mnew = fmaxf(mold, mx);
            const float alpha = __expf(mold - mnew);
            float ssum = 0.0f;
#pragma unroll
            for (int c = 0; c < 16; c++) {
                const float p = __expf(prow[c] - mnew);
                prow[c] = p;
                ssum += p;
            }
            ssum += __shfl_xor_sync(0xffffffffu, ssum, 1);
            ssum += __shfl_xor_sync(0xffffffffu, ssum, 2);
            if (part == 0) {
                msm[row] = mnew;
                alf[row] = alpha;
                lsm[row] = lsm[row] * alpha + ssum;
            }
        }
        __syncthreads();

        // O = O*alpha + P @ V via mma (k-dim = 64 keys)
        {
            const float al0 = alf[r0];
            const float al1 = alf[r1];
#pragma unroll
            for (int nt = 0; nt < 4; nt++) {
                Oacc[nt][0] *= al0;
                Oacc[nt][1] *= al0;
                Oacc[nt][2] *= al1;
                Oacc[nt][3] *= al1;
            }
#pragma unroll
            for (int ks = 0; ks < 8; ks++) {
                const int kk = ks * 8 + t4;
                uint32_t af[4];
                af[0] = f2tf32(Ps[r0 * AST + kk]);
                af[1] = f2tf32(Ps[r1 * AST + kk]);
                af[2] = f2tf32(Ps[r0 * AST + kk + 4]);
                af[3] = f2tf32(Ps[r1 * AST + kk + 4]);
#pragma unroll
                for (int nt = 0; nt < 4; nt++) {
                    const int n = wn * 32 + nt * 8 + g;
                    uint32_t bf[2];
                    bf[0] = f2tf32(Vt[n * AST + kk]);
                    bf[1] = f2tf32(Vt[n * AST + kk + 4]);
                    mma_tf32(Oacc[nt], af, bf);
                }
            }
        }
        __syncthreads();
    }

    // Normalize and write to O in [B,S,D] layout
    const int b = bh >> 4;
    const int h = bh & 15;
    const float inv0 = 1.0f / lsm[r0];
    const float inv1 = 1.0f / lsm[r1];
    const int s0 = qt * 64 + r0;
    const int s1 = qt * 64 + r1;
#pragma unroll
    for (int nt = 0; nt < 4; nt++) {
        const int c = wn * 32 + nt * 8 + t4 * 2;
        float2 o0, o1;
        o0.x = Oacc[nt][0] * inv0;
        o0.y = Oacc[nt][1] * inv0;
        o1.x = Oacc[nt][2] * inv1;
        o1.y = Oacc[nt][3] * inv1;
        *reinterpret_cast<float2*>(O + ((size_t)(b * Sc + s0)) * Dc + h * 64 + c) = o0;
        *reinterpret_cast<float2*>(O + ((size_t)(b * Sc + s1)) * Dc + h * 64 + c) = o1;
    }
}

// ---------------------------------------------------------------------------
extern "C" void kernel_launch(void* const* d_in, const int* in_sizes, int n_in,
                              void* d_out, int out_size) {
    const float* q  = (const float*)d_in[0];
    const float* k  = (const float*)d_in[1];
    const float* v  = (const float*)d_in[2];
    // d_in[3] = mask (causal implemented directly)
    const float* Wq = (const float*)d_in[4];
    const float* bq = (const float*)d_in[5];
    const float* Wk = (const float*)d_in[6];
    const float* bk = (const float*)d_in[7];
    const float* Wv = (const float*)d_in[8];
    const float* bv = (const float*)d_in[9];
    const float* Wo = (const float*)d_in[10];
    const float* bo = (const float*)d_in[11];
    float* out = (float*)d_out;

    float *Qh, *Kh, *Vh, *Att;
    cudaGetSymbolAddress((void**)&Qh, g_Qh);
    cudaGetSymbolAddress((void**)&Kh, g_Kh);
    cudaGetSymbolAddress((void**)&Vh, g_Vh);
    cudaGetSymbolAddress((void**)&Att, g_att);

    cudaFuncSetAttribute(proj_mma_kernel<true>,
                         cudaFuncAttributeMaxDynamicSharedMemorySize, PROJ_SMEM);
    cudaFuncSetAttribute(proj_mma_kernel<false>,
                         cudaFuncAttributeMaxDynamicSharedMemorySize, PROJ_SMEM);
    cudaFuncSetAttribute(attn_kernel, cudaFuncAttributeMaxDynamicSharedMemorySize,
                         ATTN_SMEM_BYTES);

    dim3 pgrid(Dc / 128, Mc / 128);  // (8, 32)
    proj_mma_kernel<true><<<pgrid, 256, PROJ_SMEM>>>(q, Wq, bq, Qh);
    proj_mma_kernel<true><<<pgrid, 256, PROJ_SMEM>>>(k, Wk, bk, Kh);
    proj_mma_kernel<true><<<pgrid, 256, PROJ_SMEM>>>(v, Wv, bv, Vh);

    dim3 agrid(Sc / 64, Bc * Hc);    // (32, 32)
    attn_kernel<<<agrid, 256, ATTN_SMEM_BYTES>>>(Qh, Kh, Vh, Att);

    proj_mma_kernel<false><<<pgrid, 256, PROJ_SMEM>>>(Att, Wo, bo, out);
}

// round 6
// speedup vs baseline: 5.8577x; 1.1990x over previous
#include <cuda_runtime.h>
#include <cuda_bf16.h>
#include <cstdint>

// Problem constants
constexpr int Bc = 2;
constexpr int Sc = 2048;
constexpr int Dc = 1024;
constexpr int Hc = 16;
constexpr int DKc = 64;
constexpr int Mc = Bc * Sc;  // 4096

// Scratch (device globals: allocation-free)
__device__ float g_Qh[(size_t)Bc * Hc * Sc * DKc];
__device__ float g_Kh[(size_t)Bc * Hc * Sc * DKc];
__device__ float g_Vh[(size_t)Bc * Hc * Sc * DKc];
__device__ float g_att[(size_t)Mc * Dc];

// ---------------------------------------------------------------------------
// Helpers
// ---------------------------------------------------------------------------
__device__ __forceinline__ uint32_t smem_u32(const void* p) {
    uint32_t a;
    asm("{ .reg .u64 t; cvta.to.shared.u64 t, %1; cvt.u32.u64 %0, t; }"
        : "=r"(a) : "l"(p));
    return a;
}
__device__ __forceinline__ void cp_async16(uint32_t s, const void* g) {
    asm volatile("cp.async.cg.shared.global [%0], [%1], 16;" :: "r"(s), "l"(g));
}
__device__ __forceinline__ void cp_commit() {
    asm volatile("cp.async.commit_group;" ::: "memory");
}
template <int N>
__device__ __forceinline__ void cp_wait() {
    asm volatile("cp.async.wait_group %0;" :: "n"(N) : "memory");
}
__device__ __forceinline__ uint32_t f2tf32(float f) {
    uint32_t u;
    asm("cvt.rna.tf32.f32 %0, %1;" : "=r"(u) : "f"(f));
    return u;
}
__device__ __forceinline__ void mma_tf32(float* C, const uint32_t* A,
                                         const uint32_t* B) {
    asm volatile(
        "mma.sync.aligned.m16n8k8.row.col.f32.tf32.tf32.f32 "
        "{%0,%1,%2,%3}, {%4,%5,%6,%7}, {%8,%9}, {%0,%1,%2,%3};"
        : "+f"(C[0]), "+f"(C[1]), "+f"(C[2]), "+f"(C[3])
        : "r"(A[0]), "r"(A[1]), "r"(A[2]), "r"(A[3]), "r"(B[0]), "r"(B[1]));
}

// ---------------------------------------------------------------------------
// Projection GEMM (tf32 mma): out[m,n] = sum_k A[m,k]*W[n,k] + bias[n]
// 128x128x32 tiles, 256 threads / 8 warps (4x2), double-buffered cp.async.
// ---------------------------------------------------------------------------
constexpr int PBK = 32;
constexpr int PSTR = PBK + 4;
constexpr int PTILE = 128 * PSTR;
constexpr int PROJ_SMEM = 4 * PTILE * 4;

template <bool HEAD>
__global__ void __launch_bounds__(256) proj_mma_kernel(const float* __restrict__ A,
                                                       const float* __restrict__ W,
                                                       const float* __restrict__ bias,
                                                       float* __restrict__ out) {
    extern __shared__ float sm[];
    const uint32_t smb = smem_u32(sm);

    const int tid = threadIdx.x;
    const int wid = tid >> 5;
    const int lid = tid & 31;
    const int g = lid >> 2;
    const int t4 = lid & 3;
    const int wm = wid & 3;
    const int wn = wid >> 2;
    const int row0 = blockIdx.y * 128;
    const int col0 = blockIdx.x * 128;

    const float* Ap = A + (size_t)row0 * Dc;
    const float* Wp = W + (size_t)col0 * Dc;

    auto load_tiles = [&](int kb, int buf) {
        const int k0 = kb * PBK;
        const uint32_t abase = smb + (uint32_t)(buf * 2 * PTILE) * 4;
        const uint32_t bbase = abase + (uint32_t)PTILE * 4;
#pragma unroll
        for (int i = 0; i < 4; i++) {
            const int ch = tid + i * 256;
            const int r = ch >> 3;
            const int c = ch & 7;
            const uint32_t so = (uint32_t)(r * PSTR + c * 4) * 4;
            cp_async16(abase + so, Ap + (size_t)r * Dc + k0 + c * 4);
            cp_async16(bbase + so, Wp + (size_t)r * Dc + k0 + c * 4);
        }
        cp_commit();
    };

    float acc[2][8][4] = {};

    load_tiles(0, 0);
    const int NKB = Dc / PBK;
    for (int kb = 0; kb < NKB; kb++) {
        const int buf = kb & 1;
        if (kb + 1 < NKB) {
            load_tiles(kb + 1, buf ^ 1);
            cp_wait<1>();
        } else {
            cp_wait<0>();
        }
        __syncthreads();

        const float* a_s = sm + buf * 2 * PTILE;
        const float* b_s = a_s + PTILE;
#pragma unroll
        for (int ks = 0; ks < 4; ks++) {
            const int kk = ks * 8 + t4;
            uint32_t af[2][4];
#pragma unroll
            for (int mt = 0; mt < 2; mt++) {
                const int r = wm * 32 + mt * 16 + g;
                af[mt][0] = f2tf32(a_s[r * PSTR + kk]);
                af[mt][1] = f2tf32(a_s[(r + 8) * PSTR + kk]);
                af[mt][2] = f2tf32(a_s[r * PSTR + kk + 4]);
                af[mt][3] = f2tf32(a_s[(r + 8) * PSTR + kk + 4]);
            }
#pragma unroll
            for (int nt = 0; nt < 8; nt++) {
                const int n = wn * 64 + nt * 8 + g;
                uint32_t bf[2];
                bf[0] = f2tf32(b_s[n * PSTR + kk]);
                bf[1] = f2tf32(b_s[n * PSTR + kk + 4]);
#pragma unroll
                for (int mt = 0; mt < 2; mt++) mma_tf32(acc[mt][nt], af[mt], bf);
            }
        }
        __syncthreads();
    }

#pragma unroll
    for (int mt = 0; mt < 2; mt++) {
#pragma unroll
        for (int half = 0; half < 2; half++) {
            const int m = row0 + wm * 32 + mt * 16 + g + half * 8;
            const int b = m >> 11;
            const int s = m & 2047;
#pragma unroll
            for (int nt = 0; nt < 8; nt++) {
                const int n = col0 + wn * 64 + nt * 8 + t4 * 2;
                float2 o;
                o.x = acc[mt][nt][half * 2 + 0] + bias[n];
                o.y = acc[mt][nt][half * 2 + 1] + bias[n + 1];
                if (HEAD) {
                    const int h = n >> 6, dk = n & 63;
                    *reinterpret_cast<float2*>(
                        out + ((size_t)((b * Hc + h) * Sc + s) << 6) + dk) = o;
                } else {
                    *reinterpret_cast<float2*>(out + (size_t)m * Dc + n) = o;
                }
            }
        }
    }
}

// ---------------------------------------------------------------------------
// Flash attention (causal), tf32 mma, pre-converted smem tiles, register
// softmax. CTA tile: 128 q-rows x 64 keys. 8 warps (4 x 2), warp tile 32x32.
// ---------------------------------------------------------------------------
constexpr int QST = 68;
constexpr int KST = 68;
constexpr int VST = 72;
constexpr int PST = 68;
constexpr int ATTN_SMEM_FLOATS =
    128 * QST + 64 * KST + 64 * VST + 128 * PST + 128 + 128 + 512;
constexpr int ATTN_SMEM_BYTES = ATTN_SMEM_FLOATS * 4;  // 108544

__global__ void __launch_bounds__(256) attn_kernel(const float* __restrict__ Qh,
                                                   const float* __restrict__ Kh,
                                                   const float* __restrict__ Vh,
                                                   float* __restrict__ O) {
    extern __shared__ float smf[];
    float* Qs  = smf;                    // [128][QST] tf32 bits, pre-scaled
    float* Ks  = Qs + 128 * QST;         // [64][KST] tf32 bits
    float* Vs  = Ks + 64 * KST;          // [64][VST] tf32 bits (row-major!)
    float* Ps  = Vs + 64 * VST;          // [128][PST] tf32 bits
    float* msm = Ps + 128 * PST;         // [128]
    float* lsm = msm + 128;              // [128]
    float* wred = lsm + 128;             // [512]: wmax[2][128], wsum[2][128]

    const uint32_t* Qu = reinterpret_cast<const uint32_t*>(Qs);
    const uint32_t* Ku = reinterpret_cast<const uint32_t*>(Ks);
    const uint32_t* Vu = reinterpret_cast<const uint32_t*>(Vs);
    const uint32_t* Pu = reinterpret_cast<const uint32_t*>(Ps);

    const int tid = threadIdx.x;
    const int wid = tid >> 5;
    const int lid = tid & 31;
    const int g = lid >> 2;
    const int t4 = lid & 3;
    const int wm = wid & 3;      // 32-row slice
    const int wn = wid >> 2;     // 32-col slice
    const int qt = blockIdx.x;
    const int bh = blockIdx.y;
    const int rb = wm * 32;

    const float* Qbase = Qh + ((size_t)bh * Sc + qt * 128) * DKc;
    const float* Kbase = Kh + (size_t)bh * Sc * DKc;
    const float* Vbase = Vh + (size_t)bh * Sc * DKc;

    // Load + scale + convert Q tile (128 x 64)
    for (int i = tid * 4; i < 128 * 64; i += 1024) {
        const int r = i >> 6, c = i & 63;
        float4 q = *reinterpret_cast<const float4*>(Qbase + i);
        uint4 u;
        u.x = f2tf32(q.x * 0.125f);
        u.y = f2tf32(q.y * 0.125f);
        u.z = f2tf32(q.z * 0.125f);
        u.w = f2tf32(q.w * 0.125f);
        *reinterpret_cast<uint4*>(Qs + r * QST + c) = u;
    }
    if (tid < 128) { msm[tid] = -1e30f; lsm[tid] = 0.0f; }

    float Oacc[2][4][4] = {};
    __syncthreads();

    const int ktmax = 2 * qt + 1;
    for (int kt = 0; kt <= ktmax; ++kt) {
        const float* Kb = Kbase + (size_t)kt * 64 * DKc;
        const float* Vb = Vbase + (size_t)kt * 64 * DKc;
        for (int i = tid * 4; i < 64 * 64; i += 1024) {
            const int r = i >> 6, c = i & 63;
            float4 k4 = *reinterpret_cast<const float4*>(Kb + i);
            uint4 ku;
            ku.x = f2tf32(k4.x); ku.y = f2tf32(k4.y);
            ku.z = f2tf32(k4.z); ku.w = f2tf32(k4.w);
            *reinterpret_cast<uint4*>(Ks + r * KST + c) = ku;
            float4 v4 = *reinterpret_cast<const float4*>(Vb + i);
            uint4 vu;
            vu.x = f2tf32(v4.x); vu.y = f2tf32(v4.y);
            vu.z = f2tf32(v4.z); vu.w = f2tf32(v4.w);
            *reinterpret_cast<uint4*>(Vs + r * VST + c) = vu;
        }
        __syncthreads();

        // S = Q @ K^T  (32x32 per warp, k-dim 64)
        float sacc[2][4][4] = {};
#pragma unroll
        for (int ks = 0; ks < 8; ks++) {
            const int kk = ks * 8 + t4;
            uint32_t af[2][4];
#pragma unroll
            for (int mt = 0; mt < 2; mt++) {
                const int r0 = rb + mt * 16 + g;
                af[mt][0] = Qu[r0 * QST + kk];
                af[mt][1] = Qu[(r0 + 8) * QST + kk];
                af[mt][2] = Qu[r0 * QST + kk + 4];
                af[mt][3] = Qu[(r0 + 8) * QST + kk + 4];
            }
#pragma unroll
            for (int nt = 0; nt < 4; nt++) {
                const int n = wn * 32 + nt * 8 + g;
                uint32_t bf[2];
                bf[0] = Ku[n * KST + kk];
                bf[1] = Ku[n * KST + kk + 4];
#pragma unroll
                for (int mt = 0; mt < 2; mt++) mma_tf32(sacc[mt][nt], af[mt], bf);
            }
        }

        // causal mask (register-side)
        if (kt >= 2 * qt) {
            const int cbase = kt * 64 + wn * 32;
            const int rgb = qt * 128 + rb;
#pragma unroll
            for (int mt = 0; mt < 2; mt++) {
                const int r00 = rgb + mt * 16 + g;
                const int r01 = r00 + 8;
#pragma unroll
                for (int nt = 0; nt < 4; nt++) {
                    const int c0 = cbase + nt * 8 + 2 * t4;
                    if (c0 > r00)     sacc[mt][nt][0] = -1e30f;
                    if (c0 + 1 > r00) sacc[mt][nt][1] = -1e30f;
                    if (c0 > r01)     sacc[mt][nt][2] = -1e30f;
                    if (c0 + 1 > r01) sacc[mt][nt][3] = -1e30f;
                }
            }
        }

        // per-row partial max (register + shfl over t4 quad)
        float pm[2][2];
#pragma unroll
        for (int mt = 0; mt < 2; mt++) {
            float m0 = -1e30f, m1 = -1e30f;
#pragma unroll
            for (int nt = 0; nt < 4; nt++) {
                m0 = fmaxf(m0, fmaxf(sacc[mt][nt][0], sacc[mt][nt][1]));
                m1 = fmaxf(m1, fmaxf(sacc[mt][nt][2], sacc[mt][nt][3]));
            }
            pm[mt][0] = m0;
            pm[mt][1] = m1;
        }
#pragma unroll
        for (int mt = 0; mt < 2; mt++)
#pragma unroll
            for (int hh = 0; hh < 2; hh++) {
                pm[mt][hh] = fmaxf(pm[mt][hh], __shfl_xor_sync(0xffffffffu, pm[mt][hh], 1));
                pm[mt][hh] = fmaxf(pm[mt][hh], __shfl_xor_sync(0xffffffffu, pm[mt][hh], 2));
            }
        if (t4 == 0) {
#pragma unroll
            for (int mt = 0; mt < 2; mt++)
#pragma unroll
                for (int hh = 0; hh < 2; hh++)
                    wred[wn * 128 + rb + mt * 16 + hh * 8 + g] = pm[mt][hh];
        }
        __syncthreads();

        // mnew / alpha per lane-row
        float mnew[2][2], alpha[2][2];
#pragma unroll
        for (int mt = 0; mt < 2; mt++)
#pragma unroll
            for (int hh = 0; hh < 2; hh++) {
                const int row = rb + mt * 16 + hh * 8 + g;
                const float mold = msm[row];
                const float mn = fmaxf(mold, fmaxf(wred[row], wred[128 + row]));
                mnew[mt][hh] = mn;
                alpha[mt][hh] = __expf(mold - mn);
            }

        // exp (registers), P write (pre-converted), partial sums
        float psum[2][2] = {};
#pragma unroll
        for (int mt = 0; mt < 2; mt++) {
            const int row0 = rb + mt * 16 + g;
            const int row1 = row0 + 8;
#pragma unroll
            for (int nt = 0; nt < 4; nt++) {
                const int c = wn * 32 + nt * 8 + 2 * t4;
                const float p0 = __expf(sacc[mt][nt][0] - mnew[mt][0]);
                const float p1 = __expf(sacc[mt][nt][1] - mnew[mt][0]);
                const float p2 = __expf(sacc[mt][nt][2] - mnew[mt][1]);
                const float p3 = __expf(sacc[mt][nt][3] - mnew[mt][1]);
                psum[mt][0] += p0 + p1;
                psum[mt][1] += p2 + p3;
                float2 w0, w1;
                w0.x = __uint_as_float(f2tf32(p0));
                w0.y = __uint_as_float(f2tf32(p1));
                w1.x = __uint_as_float(f2tf32(p2));
                w1.y = __uint_as_float(f2tf32(p3));
                *reinterpret_cast<float2*>(Ps + row0 * PST + c) = w0;
                *reinterpret_cast<float2*>(Ps + row1 * PST + c) = w1;
            }
        }
#pragma unroll
        for (int mt = 0; mt < 2; mt++)
#pragma unroll
            for (int hh = 0; hh < 2; hh++) {
                psum[mt][hh] += __shfl_xor_sync(0xffffffffu, psum[mt][hh], 1);
                psum[mt][hh] += __shfl_xor_sync(0xffffffffu, psum[mt][hh], 2);
            }
        if (t4 == 0) {
#pragma unroll
            for (int mt = 0; mt < 2; mt++)
#pragma unroll
                for (int hh = 0; hh < 2; hh++)
                    wred[256 + wn * 128 + rb + mt * 16 + hh * 8 + g] = psum[mt][hh];
        }
        __syncthreads();

        // row bookkeeping (one thread per row)
        if (tid < 128) {
            const int row = tid;
            const float mold = msm[row];
            const float mn = fmaxf(mold, fmaxf(wred[row], wred[128 + row]));
            lsm[row] = lsm[row] * __expf(mold - mn) + wred[256 + row] + wred[384 + row];
            msm[row] = mn;
        }

        // O = O*alpha + P @ V
#pragma unroll
        for (int mt = 0; mt < 2; mt++)
#pragma unroll
            for (int nt = 0; nt < 4; nt++) {
                Oacc[mt][nt][0] *= alpha[mt][0];
                Oacc[mt][nt][1] *= alpha[mt][0];
                Oacc[mt][nt][2] *= alpha[mt][1];
                Oacc[mt][nt][3] *= alpha[mt][1];
            }
#pragma unroll
        for (int ks = 0; ks < 8; ks++) {
            const int kk = ks * 8 + t4;
            uint32_t af[2][4];
#pragma unroll
            for (int mt = 0; mt < 2; mt++) {
                const int r0 = rb + mt * 16 + g;
                af[mt][0] = Pu[r0 * PST + kk];
                af[mt][1] = Pu[(r0 + 8) * PST + kk];
                af[mt][2] = Pu[r0 * PST + kk + 4];
                af[mt][3] = Pu[(r0 + 8) * PST + kk + 4];
            }
#pragma unroll
            for (int nt = 0; nt < 4; nt++) {
                const int n = wn * 32 + nt * 8 + g;
                uint32_t bf[2];
                bf[0] = Vu[kk * VST + n];
                bf[1] = Vu[(kk + 4) * VST + n];
#pragma unroll
                for (int mt = 0; mt < 2; mt++) mma_tf32(Oacc[mt][nt], af[mt], bf);
            }
        }
        __syncthreads();
    }

    // Epilogue: normalize and write to O in [B,S,D] layout
    const int b = bh >> 4;
    const int h = bh & 15;
#pragma unroll
    for (int mt = 0; mt < 2; mt++)
#pragma unroll
        for (int hh = 0; hh < 2; hh++) {
            const int row = rb + mt * 16 + hh * 8 + g;
            const float inv = 1.0f / lsm[row];
            const int s = qt * 128 + row;
#pragma unroll
            for (int nt = 0; nt < 4; nt++) {
                const int c = wn * 32 + nt * 8 + 2 * t4;
                float2 o;
                o.x = Oacc[mt][nt][hh * 2 + 0] * inv;
                o.y = Oacc[mt][nt][hh * 2 + 1] * inv;
                *reinterpret_cast<float2*>(
                    O + ((size_t)(b * Sc + s)) * Dc + h * 64 + c) = o;
            }
        }
}

// ---------------------------------------------------------------------------
extern "C" void kernel_launch(void* const* d_in, const int* in_sizes, int n_in,
                              void* d_out, int out_size) {
    const float* q  = (const float*)d_in[0];
    const float* k  = (const float*)d_in[1];
    const float* v  = (const float*)d_in[2];
    // d_in[3] = mask (causal implemented directly)
    const float* Wq = (const float*)d_in[4];
    const float* bq = (const float*)d_in[5];
    const float* Wk = (const float*)d_in[6];
    const float* bk = (const float*)d_in[7];
    const float* Wv = (const float*)d_in[8];
    const float* bv = (const float*)d_in[9];
    const float* Wo = (const float*)d_in[10];
    const float* bo = (const float*)d_in[11];
    float* out = (float*)d_out;

    float *Qh, *Kh, *Vh, *Att;
    cudaGetSymbolAddress((void**)&Qh, g_Qh);
    cudaGetSymbolAddress((void**)&Kh, g_Kh);
    cudaGetSymbolAddress((void**)&Vh, g_Vh);
    cudaGetSymbolAddress((void**)&Att, g_att);

    cudaFuncSetAttribute(proj_mma_kernel<true>,
                         cudaFuncAttributeMaxDynamicSharedMemorySize, PROJ_SMEM);
    cudaFuncSetAttribute(proj_mma_kernel<false>,
                         cudaFuncAttributeMaxDynamicSharedMemorySize, PROJ_SMEM);
    cudaFuncSetAttribute(attn_kernel, cudaFuncAttributeMaxDynamicSharedMemorySize,
                         ATTN_SMEM_BYTES);

    dim3 pgrid(Dc / 128, Mc / 128);  // (8, 32)
    proj_mma_kernel<true><<<pgrid, 256, PROJ_SMEM>>>(q, Wq, bq, Qh);
    proj_mma_kernel<true><<<pgrid, 256, PROJ_SMEM>>>(k, Wk, bk, Kh);
    proj_mma_kernel<true><<<pgrid, 256, PROJ_SMEM>>>(v, Wv, bv, Vh);

    dim3 agrid(Sc / 128, Bc * Hc);   // (16, 32)
    attn_kernel<<<agrid, 256, ATTN_SMEM_BYTES>>>(Qh, Kh, Vh, Att);

    proj_mma_kernel<false><<<pgrid, 256, PROJ_SMEM>>>(Att, Wo, bo, out);
}

// round 7
// speedup vs baseline: 5.9118x; 1.0092x over previous
#include <cuda_runtime.h>
#include <cuda_bf16.h>
#include <cstdint>

// Problem constants
constexpr int Bc = 2;
constexpr int Sc = 2048;
constexpr int Dc = 1024;
constexpr int Hc = 16;
constexpr int DKc = 64;
constexpr int Mc = Bc * Sc;  // 4096

// Scratch (device globals: allocation-free)
__device__ float g_Qh[(size_t)Bc * Hc * Sc * DKc];
__device__ float g_Kh[(size_t)Bc * Hc * Sc * DKc];
__device__ float g_Vh[(size_t)Bc * Hc * Sc * DKc];
__device__ float g_att[(size_t)Mc * Dc];

// ---------------------------------------------------------------------------
// Helpers
// ---------------------------------------------------------------------------
__device__ __forceinline__ uint32_t smem_u32(const void* p) {
    uint32_t a;
    asm("{ .reg .u64 t; cvta.to.shared.u64 t, %1; cvt.u32.u64 %0, t; }"
        : "=r"(a) : "l"(p));
    return a;
}
__device__ __forceinline__ void cp_async16(uint32_t s, const void* g) {
    asm volatile("cp.async.cg.shared.global [%0], [%1], 16;" :: "r"(s), "l"(g));
}
__device__ __forceinline__ void cp_commit() {
    asm volatile("cp.async.commit_group;" ::: "memory");
}
template <int N>
__device__ __forceinline__ void cp_wait() {
    asm volatile("cp.async.wait_group %0;" :: "n"(N) : "memory");
}
__device__ __forceinline__ uint32_t f2tf32(float f) {
    uint32_t u;
    asm("cvt.rna.tf32.f32 %0, %1;" : "=r"(u) : "f"(f));
    return u;
}
__device__ __forceinline__ void mma_tf32(float* C, const uint32_t* A,
                                         const uint32_t* B) {
    asm volatile(
        "mma.sync.aligned.m16n8k8.row.col.f32.tf32.tf32.f32 "
        "{%0,%1,%2,%3}, {%4,%5,%6,%7}, {%8,%9}, {%0,%1,%2,%3};"
        : "+f"(C[0]), "+f"(C[1]), "+f"(C[2]), "+f"(C[3])
        : "r"(A[0]), "r"(A[1]), "r"(A[2]), "r"(A[3]), "r"(B[0]), "r"(B[1]));
}

// ---------------------------------------------------------------------------
// Projection GEMM core (tf32 mma): out[m,n] = sum_k A[m,k]*W[n,k] + bias[n]
// 128x128x32 tiles, 256 threads / 8 warps (4x2), double-buffered cp.async.
// ---------------------------------------------------------------------------
constexpr int PBK = 32;
constexpr int PSTR = PBK + 4;
constexpr int PTILE = 128 * PSTR;
constexpr int PROJ_SMEM = 4 * PTILE * 4;

template <bool HEAD>
__device__ __forceinline__ void proj_body(const float* __restrict__ A,
                                          const float* __restrict__ W,
                                          const float* __restrict__ bias,
                                          float* __restrict__ out,
                                          float* sm, int row0, int col0) {
    const uint32_t smb = smem_u32(sm);
    const int tid = threadIdx.x;
    const int wid = tid >> 5;
    const int lid = tid & 31;
    const int g = lid >> 2;
    const int t4 = lid & 3;
    const int wm = wid & 3;
    const int wn = wid >> 2;

    const float* Ap = A + (size_t)row0 * Dc;
    const float* Wp = W + (size_t)col0 * Dc;

    auto load_tiles = [&](int kb, int buf) {
        const int k0 = kb * PBK;
        const uint32_t abase = smb + (uint32_t)(buf * 2 * PTILE) * 4;
        const uint32_t bbase = abase + (uint32_t)PTILE * 4;
#pragma unroll
        for (int i = 0; i < 4; i++) {
            const int ch = tid + i * 256;
            const int r = ch >> 3;
            const int c = ch & 7;
            const uint32_t so = (uint32_t)(r * PSTR + c * 4) * 4;
            cp_async16(abase + so, Ap + (size_t)r * Dc + k0 + c * 4);
            cp_async16(bbase + so, Wp + (size_t)r * Dc + k0 + c * 4);
        }
        cp_commit();
    };

    float acc[2][8][4] = {};

    load_tiles(0, 0);
    const int NKB = Dc / PBK;
    for (int kb = 0; kb < NKB; kb++) {
        const int buf = kb & 1;
        if (kb + 1 < NKB) {
            load_tiles(kb + 1, buf ^ 1);
            cp_wait<1>();
        } else {
            cp_wait<0>();
        }
        __syncthreads();

        const float* a_s = sm + buf * 2 * PTILE;
        const float* b_s = a_s + PTILE;
#pragma unroll
        for (int ks = 0; ks < 4; ks++) {
            const int kk = ks * 8 + t4;
            uint32_t af[2][4];
#pragma unroll
            for (int mt = 0; mt < 2; mt++) {
                const int r = wm * 32 + mt * 16 + g;
                af[mt][0] = f2tf32(a_s[r * PSTR + kk]);
                af[mt][1] = f2tf32(a_s[(r + 8) * PSTR + kk]);
                af[mt][2] = f2tf32(a_s[r * PSTR + kk + 4]);
                af[mt][3] = f2tf32(a_s[(r + 8) * PSTR + kk + 4]);
            }
#pragma unroll
            for (int nt = 0; nt < 8; nt++) {
                const int n = wn * 64 + nt * 8 + g;
                uint32_t bf[2];
                bf[0] = f2tf32(b_s[n * PSTR + kk]);
                bf[1] = f2tf32(b_s[n * PSTR + kk + 4]);
#pragma unroll
                for (int mt = 0; mt < 2; mt++) mma_tf32(acc[mt][nt], af[mt], bf);
            }
        }
        __syncthreads();
    }

#pragma unroll
    for (int mt = 0; mt < 2; mt++) {
#pragma unroll
        for (int half = 0; half < 2; half++) {
            const int m = row0 + wm * 32 + mt * 16 + g + half * 8;
            const int b = m >> 11;
            const int s = m & 2047;
#pragma unroll
            for (int nt = 0; nt < 8; nt++) {
                const int n = col0 + wn * 64 + nt * 8 + t4 * 2;
                float2 o;
                o.x = acc[mt][nt][half * 2 + 0] + bias[n];
                o.y = acc[mt][nt][half * 2 + 1] + bias[n + 1];
                if (HEAD) {
                    const int h = n >> 6, dk = n & 63;
                    *reinterpret_cast<float2*>(
                        out + ((size_t)((b * Hc + h) * Sc + s) << 6) + dk) = o;
                } else {
                    *reinterpret_cast<float2*>(out + (size_t)m * Dc + n) = o;
                }
            }
        }
    }
}

// Merged Q/K/V projection: blockIdx.z selects which projection.
__global__ void __launch_bounds__(256) proj_qkv_kernel(
    const float* __restrict__ q, const float* __restrict__ k,
    const float* __restrict__ v,
    const float* __restrict__ Wq, const float* __restrict__ bq,
    const float* __restrict__ Wk, const float* __restrict__ bk,
    const float* __restrict__ Wv, const float* __restrict__ bv,
    float* __restrict__ Qh, float* __restrict__ Kh, float* __restrict__ Vh) {
    extern __shared__ float sm[];
    const int z = blockIdx.z;
    const float* A = (z == 0) ? q : (z == 1) ? k : v;
    const float* W = (z == 0) ? Wq : (z == 1) ? Wk : Wv;
    const float* bias = (z == 0) ? bq : (z == 1) ? bk : bv;
    float* out = (z == 0) ? Qh : (z == 1) ? Kh : Vh;
    proj_body<true>(A, W, bias, out, sm, blockIdx.y * 128, blockIdx.x * 128);
}

// Output projection.
__global__ void __launch_bounds__(256) proj_o_kernel(const float* __restrict__ A,
                                                     const float* __restrict__ W,
                                                     const float* __restrict__ bias,
                                                     float* __restrict__ out) {
    extern __shared__ float sm[];
    proj_body<false>(A, W, bias, out, sm, blockIdx.y * 128, blockIdx.x * 128);
}

// ---------------------------------------------------------------------------
// Flash attention (causal), tf32 mma, row-owning warps.
// CTA: 128 q-rows x 64-key tiles, 8 warps x 16 rows. Q in register fragments,
// softmax fully intra-warp, P through warp-private smem (syncwarp only).
// ---------------------------------------------------------------------------
constexpr int KST = 68;   // K row stride (floats)
constexpr int VST = 72;   // V row stride
constexpr int PSTW = 68;  // P / Q-staging row stride
constexpr int ATTN_SMEM_FLOATS = 64 * KST + 64 * VST + 128 * PSTW;  // 17664
constexpr int ATTN_SMEM_BYTES = ATTN_SMEM_FLOATS * 4;               // 70656

__global__ void __launch_bounds__(256, 2) attn_kernel(const float* __restrict__ Qh,
                                                      const float* __restrict__ Kh,
                                                      const float* __restrict__ Vh,
                                                      float* __restrict__ O) {
    extern __shared__ float smf[];
    float* Ks = smf;                 // [64][KST] tf32 bits
    float* Vs = Ks + 64 * KST;       // [64][VST] tf32 bits (row-major)
    float* Pall = Vs + 64 * VST;     // [128][PSTW]: Q staging, then per-warp P

    const uint32_t* Ku = reinterpret_cast<const uint32_t*>(Ks);
    const uint32_t* Vu = reinterpret_cast<const uint32_t*>(Vs);

    const int tid = threadIdx.x;
    const int wid = tid >> 5;
    const int lid = tid & 31;
    const int g = lid >> 2;
    const int t4 = lid & 3;
    const int qt = blockIdx.x;
    const int bh = blockIdx.y;
    const int rb = wid * 16;  // warp's 16-row slice

    const float* Qbase = Qh + ((size_t)bh * Sc + qt * 128) * DKc;
    const float* Kbase = Kh + (size_t)bh * Sc * DKc;
    const float* Vbase = Vh + (size_t)bh * Sc * DKc;

    // Stage Q tile (scaled + tf32) into Pall as [128][PSTW]
    for (int i = tid * 4; i < 128 * 64; i += 1024) {
        const int r = i >> 6, c = i & 63;
        float4 q = *reinterpret_cast<const float4*>(Qbase + i);
        uint4 u;
        u.x = f2tf32(q.x * 0.125f);
        u.y = f2tf32(q.y * 0.125f);
        u.z = f2tf32(q.z * 0.125f);
        u.w = f2tf32(q.w * 0.125f);
        *reinterpret_cast<uint4*>(Pall + r * PSTW + c) = u;
    }
    __syncthreads();

    // Read Q fragments into registers (32 regs)
    uint32_t qf[8][4];
    {
        const uint32_t* Pu = reinterpret_cast<const uint32_t*>(Pall);
#pragma unroll
        for (int ks = 0; ks < 8; ks++) {
            const int kk = ks * 8 + t4;
            qf[ks][0] = Pu[(rb + g) * PSTW + kk];
            qf[ks][1] = Pu[(rb + g + 8) * PSTW + kk];
            qf[ks][2] = Pu[(rb + g) * PSTW + kk + 4];
            qf[ks][3] = Pu[(rb + g + 8) * PSTW + kk + 4];
        }
    }

    // Warp-private P buffer
    float* Pw = Pall + wid * 16 * PSTW;
    uint32_t* Pwu = reinterpret_cast<uint32_t*>(Pw);

    float m0 = -1e30f, m1 = -1e30f, l0 = 0.0f, l1 = 0.0f;
    float Oacc[8][4] = {};

    const int ktmax = 2 * qt + 1;
    for (int kt = 0; kt <= ktmax; ++kt) {
        __syncthreads();  // all warps done with previous K/V (and Q staging)
        const float* Kb = Kbase + (size_t)kt * 64 * DKc;
        const float* Vb = Vbase + (size_t)kt * 64 * DKc;
        for (int i = tid * 4; i < 64 * 64; i += 1024) {
            const int r = i >> 6, c = i & 63;
            float4 k4 = *reinterpret_cast<const float4*>(Kb + i);
            uint4 ku;
            ku.x = f2tf32(k4.x); ku.y = f2tf32(k4.y);
            ku.z = f2tf32(k4.z); ku.w = f2tf32(k4.w);
            *reinterpret_cast<uint4*>(Ks + r * KST + c) = ku;
            float4 v4 = *reinterpret_cast<const float4*>(Vb + i);
            uint4 vu;
            vu.x = f2tf32(v4.x); vu.y = f2tf32(v4.y);
            vu.z = f2tf32(v4.z); vu.w = f2tf32(v4.w);
            *reinterpret_cast<uint4*>(Vs + r * VST + c) = vu;
        }
        __syncthreads();  // K/V ready

        // S = Q @ K^T : warp tile 16 rows x 64 keys, k-dim 64
        float sacc[8][4] = {};
#pragma unroll
        for (int ks = 0; ks < 8; ks++) {
            const int kk = ks * 8 + t4;
#pragma unroll
            for (int nt = 0; nt < 8; nt++) {
                const int n = nt * 8 + g;
                uint32_t bf[2];
                bf[0] = Ku[n * KST + kk];
                bf[1] = Ku[n * KST + kk + 4];
                mma_tf32(sacc[nt], qf[ks], bf);
            }
        }

        // causal mask
        if (kt >= 2 * qt) {
            const int cb = kt * 64;
            const int r0g = qt * 128 + rb + g;
            const int r1g = r0g + 8;
#pragma unroll
            for (int nt = 0; nt < 8; nt++) {
                const int c0 = cb + nt * 8 + 2 * t4;
                if (c0 > r0g)     sacc[nt][0] = -1e30f;
                if (c0 + 1 > r0g) sacc[nt][1] = -1e30f;
                if (c0 > r1g)     sacc[nt][2] = -1e30f;
                if (c0 + 1 > r1g) sacc[nt][3] = -1e30f;
            }
        }

        // row max (16 local values + quad shfl)
        float pm0 = -1e30f, pm1 = -1e30f;
#pragma unroll
        for (int nt = 0; nt < 8; nt++) {
            pm0 = fmaxf(pm0, fmaxf(sacc[nt][0], sacc[nt][1]));
            pm1 = fmaxf(pm1, fmaxf(sacc[nt][2], sacc[nt][3]));
        }
        pm0 = fmaxf(pm0, __shfl_xor_sync(0xffffffffu, pm0, 1));
        pm0 = fmaxf(pm0, __shfl_xor_sync(0xffffffffu, pm0, 2));
        pm1 = fmaxf(pm1, __shfl_xor_sync(0xffffffffu, pm1, 1));
        pm1 = fmaxf(pm1, __shfl_xor_sync(0xffffffffu, pm1, 2));

        const float mn0 = fmaxf(m0, pm0);
        const float mn1 = fmaxf(m1, pm1);
        const float a0 = __expf(m0 - mn0);
        const float a1 = __expf(m1 - mn1);
        m0 = mn0;
        m1 = mn1;

        // exp, P write (tf32), partial sums
        float ps0 = 0.0f, ps1 = 0.0f;
#pragma unroll
        for (int nt = 0; nt < 8; nt++) {
            const int c = nt * 8 + 2 * t4;
            const float p0 = __expf(sacc[nt][0] - mn0);
            const float p1 = __expf(sacc[nt][1] - mn0);
            const float p2 = __expf(sacc[nt][2] - mn1);
            const float p3 = __expf(sacc[nt][3] - mn1);
            ps0 += p0 + p1;
            ps1 += p2 + p3;
            float2 w0, w1;
            w0.x = __uint_as_float(f2tf32(p0));
            w0.y = __uint_as_float(f2tf32(p1));
            w1.x = __uint_as_float(f2tf32(p2));
            w1.y = __uint_as_float(f2tf32(p3));
            *reinterpret_cast<float2*>(Pw + g * PSTW + c) = w0;
            *reinterpret_cast<float2*>(Pw + (g + 8) * PSTW + c) = w1;
        }
        ps0 += __shfl_xor_sync(0xffffffffu, ps0, 1);
        ps0 += __shfl_xor_sync(0xffffffffu, ps0, 2);
        ps1 += __shfl_xor_sync(0xffffffffu, ps1, 1);
        ps1 += __shfl_xor_sync(0xffffffffu, ps1, 2);
        l0 = l0 * a0 + ps0;
        l1 = l1 * a1 + ps1;

        // rescale O
#pragma unroll
        for (int nt = 0; nt < 8; nt++) {
            Oacc[nt][0] *= a0;
            Oacc[nt][1] *= a0;
            Oacc[nt][2] *= a1;
            Oacc[nt][3] *= a1;
        }
        __syncwarp();

        // O += P @ V : k-dim 64 keys, n-dim 64 dk
#pragma unroll
        for (int ks = 0; ks < 8; ks++) {
            const int kk = ks * 8 + t4;
            uint32_t af[4];
            af[0] = Pwu[g * PSTW + kk];
            af[1] = Pwu[(g + 8) * PSTW + kk];
            af[2] = Pwu[g * PSTW + kk + 4];
            af[3] = Pwu[(g + 8) * PSTW + kk + 4];
#pragma unroll
            for (int nt = 0; nt < 8; nt++) {
                const int n = nt * 8 + g;
                uint32_t bf[2];
                bf[0] = Vu[kk * VST + n];
                bf[1] = Vu[(kk + 4) * VST + n];
                mma_tf32(Oacc[nt], af, bf);
            }
        }
        __syncwarp();  // PV reads done before next iteration's P writes
    }

    // Epilogue: normalize and write [B,S,D]
    const int b = bh >> 4;
    const int h = bh & 15;
    const float inv0 = 1.0f / l0;
    const float inv1 = 1.0f / l1;
    const int s0 = qt * 128 + rb + g;
    const int s1 = s0 + 8;
#pragma unroll
    for (int nt = 0; nt < 8; nt++) {
        const int c = nt * 8 + 2 * t4;
        float2 o0, o1;
        o0.x = Oacc[nt][0] * inv0;
        o0.y = Oacc[nt][1] * inv0;
        o1.x = Oacc[nt][2] * inv1;
        o1.y = Oacc[nt][3] * inv1;
        *reinterpret_cast<float2*>(O + ((size_t)(b * Sc + s0)) * Dc + h * 64 + c) = o0;
        *reinterpret_cast<float2*>(O + ((size_t)(b * Sc + s1)) * Dc + h * 64 + c) = o1;
    }
}

// ---------------------------------------------------------------------------
extern "C" void kernel_launch(void* const* d_in, const int* in_sizes, int n_in,
                              void* d_out, int out_size) {
    const float* q  = (const float*)d_in[0];
    const float* k  = (const float*)d_in[1];
    const float* v  = (const float*)d_in[2];
    // d_in[3] = mask (causal implemented directly)
    const float* Wq = (const float*)d_in[4];
    const float* bq = (const float*)d_in[5];
    const float* Wk = (const float*)d_in[6];
    const float* bk = (const float*)d_in[7];
    const float* Wv = (const float*)d_in[8];
    const float* bv = (const float*)d_in[9];
    const float* Wo = (const float*)d_in[10];
    const float* bo = (const float*)d_in[11];
    float* out = (float*)d_out;

    float *Qh, *Kh, *Vh, *Att;
    cudaGetSymbolAddress((void**)&Qh, g_Qh);
    cudaGetSymbolAddress((void**)&Kh, g_Kh);
    cudaGetSymbolAddress((void**)&Vh, g_Vh);
    cudaGetSymbolAddress((void**)&Att, g_att);

    cudaFuncSetAttribute(proj_qkv_kernel,
                         cudaFuncAttributeMaxDynamicSharedMemorySize, PROJ_SMEM);
    cudaFuncSetAttribute(proj_o_kernel,
                         cudaFuncAttributeMaxDynamicSharedMemorySize, PROJ_SMEM);
    cudaFuncSetAttribute(attn_kernel, cudaFuncAttributeMaxDynamicSharedMemorySize,
                         ATTN_SMEM_BYTES);

    dim3 qkvgrid(Dc / 128, Mc / 128, 3);  // (8, 32, 3)
    proj_qkv_kernel<<<qkvgrid, 256, PROJ_SMEM>>>(q, k, v, Wq, bq, Wk, bk, Wv, bv,
                                                 Qh, Kh, Vh);

    dim3 agrid(Sc / 128, Bc * Hc);        // (16, 32)
    attn_kernel<<<agrid, 256, ATTN_SMEM_BYTES>>>(Qh, Kh, Vh, Att);

    dim3 ogrid(Dc / 128, Mc / 128);       // (8, 32)
    proj_o_kernel<<<ogrid, 256, PROJ_SMEM>>>(Att, Wo, bo, out);
}

// round 9
// speedup vs baseline: 11.5391x; 1.9519x over previous
#include <cuda_runtime.h>
#include <cuda_fp16.h>
#include <cstdint>

// Problem constants
constexpr int Bc = 2;
constexpr int Sc = 2048;
constexpr int Dc = 1024;
constexpr int Hc = 16;
constexpr int DKc = 64;
constexpr int Mc = Bc * Sc;  // 4096

// Half scratch (device globals: allocation-free)
__device__ __half g_q16[(size_t)Mc * Dc];
__device__ __half g_k16[(size_t)Mc * Dc];
__device__ __half g_v16[(size_t)Mc * Dc];
__device__ __half g_Wq16[(size_t)Dc * Dc];
__device__ __half g_Wk16[(size_t)Dc * Dc];
__device__ __half g_Wv16[(size_t)Dc * Dc];
__device__ __half g_Wo16[(size_t)Dc * Dc];
__device__ __half g_Qh[(size_t)Bc * Hc * Sc * DKc];   // [b,h,s,dk]
__device__ __half g_Kh[(size_t)Bc * Hc * Sc * DKc];   // [b,h,s,dk]
__device__ __half g_Vt[(size_t)Bc * Hc * DKc * Sc];   // [b,h,dk,s] (transposed)
__device__ __half g_att[(size_t)Mc * Dc];             // [b,s,d]

// ---------------------------------------------------------------------------
// Helpers
// ---------------------------------------------------------------------------
__device__ __forceinline__ uint32_t smem_u32(const void* p) {
    uint32_t a;
    asm("{ .reg .u64 t; cvta.to.shared.u64 t, %1; cvt.u32.u64 %0, t; }"
        : "=r"(a) : "l"(p));
    return a;
}
__device__ __forceinline__ void cp_async16(uint32_t s, const void* g) {
    asm volatile("cp.async.cg.shared.global [%0], [%1], 16;" :: "r"(s), "l"(g));
}
__device__ __forceinline__ void cp_commit() {
    asm volatile("cp.async.commit_group;" ::: "memory");
}
template <int N>
__device__ __forceinline__ void cp_wait() {
    asm volatile("cp.async.wait_group %0;" :: "n"(N) : "memory");
}
__device__ __forceinline__ uint32_t pack_h2(float a, float b) {
    __half2 h = __floats2half2_rn(a, b);
    return *reinterpret_cast<uint32_t*>(&h);
}
__device__ __forceinline__ void mma_f16(float* C, const uint32_t* A,
                                        const uint32_t* B) {
    asm volatile(
        "mma.sync.aligned.m16n8k16.row.col.f32.f16.f16.f32 "
        "{%0,%1,%2,%3}, {%4,%5,%6,%7}, {%8,%9}, {%0,%1,%2,%3};"
        : "+f"(C[0]), "+f"(C[1]), "+f"(C[2]), "+f"(C[3])
        : "r"(A[0]), "r"(A[1]), "r"(A[2]), "r"(A[3]), "r"(B[0]), "r"(B[1]));
}

// ---------------------------------------------------------------------------
// Prepass: fp32 -> fp16 conversion of inputs + weights.
// Tasks in float4 units: q,k,v = 1048576 each; Wq,Wk,Wv,Wo = 262144 each.
// ---------------------------------------------------------------------------
__global__ void __launch_bounds__(256) cvt_kernel(const float* __restrict__ q,
                                                  const float* __restrict__ k,
                                                  const float* __restrict__ v,
                                                  const float* __restrict__ Wq,
                                                  const float* __restrict__ Wk,
                                                  const float* __restrict__ Wv,
                                                  const float* __restrict__ Wo) {
    constexpr size_t NIN = 1048576;   // float4 per input
    constexpr size_t NW = 262144;     // float4 per weight
    const size_t total = 3 * NIN + 4 * NW;
    for (size_t idx = blockIdx.x * 256 + threadIdx.x; idx < total;
         idx += (size_t)gridDim.x * 256) {
        const float* src;
        __half* dst;
        size_t off;
        if (idx < 3 * NIN) {
            const int w = (int)(idx / NIN);
            off = idx % NIN;
            src = (w == 0) ? q : (w == 1) ? k : v;
            dst = (w == 0) ? g_q16 : (w == 1) ? g_k16 : g_v16;
        } else {
            const size_t r = idx - 3 * NIN;
            const int w = (int)(r / NW);
            off = r % NW;
            src = (w == 0) ? Wq : (w == 1) ? Wk : (w == 2) ? Wv : Wo;
            dst = (w == 0) ? g_Wq16 : (w == 1) ? g_Wk16 : (w == 2) ? g_Wv16 : g_Wo16;
        }
        float4 f = reinterpret_cast<const float4*>(src)[off];
        uint2 u;
        u.x = pack_h2(f.x, f.y);
        u.y = pack_h2(f.z, f.w);
        reinterpret_cast<uint2*>(dst)[off] = u;
    }
}

// ---------------------------------------------------------------------------
// fp16 projection GEMM: out[m,n] = sum_k A[m,k]*W[n,k] + bias[n]
// A,W half [*,1024]. CTA 128x128, BK=64 halfs, double-buffered cp.async,
// 256 threads / 8 warps (4m x 2n), warp tile 32x64. m16n8k16.
// MODE 0: fp32 row-major out + bias (final output)
// MODE 1: half [b,h,s,dk] out (Q,K)
// MODE 2: half [b,h,dk,s] out (V transposed)
// ---------------------------------------------------------------------------
constexpr int PBKH = 64;                  // halfs per k-block
constexpr int PSTRH = 72;                 // half stride per row
constexpr int PTILEH = 128 * PSTRH;       // halfs per tile (9216)
constexpr int PROJ_SMEM = 4 * PTILEH * 2; // 73728 B

template <int MODE>
__device__ __forceinline__ void proj_body(const __half* __restrict__ A,
                                          const __half* __restrict__ W,
                                          const float* __restrict__ bias,
                                          void* __restrict__ outp,
                                          __half* sm, int row0, int col0) {
    const uint32_t smb = smem_u32(sm);
    const int tid = threadIdx.x;
    const int wid = tid >> 5;
    const int lid = tid & 31;
    const int g = lid >> 2;
    const int t4 = lid & 3;
    const int wm = wid & 3;
    const int wn = wid >> 2;

    const __half* Ap = A + (size_t)row0 * Dc;
    const __half* Wp = W + (size_t)col0 * Dc;

    // per tile: 128 rows x 64 halfs = 1024 x 16B chunks, 4/thread
    auto load_tiles = [&](int kb, int buf) {
        const int k0 = kb * PBKH;
        const uint32_t abase = smb + (uint32_t)(buf * 2 * PTILEH) * 2;
        const uint32_t bbase = abase + (uint32_t)PTILEH * 2;
#pragma unroll
        for (int i = 0; i < 4; i++) {
            const int ch = tid + i * 256;
            const int r = ch >> 3;
            const int c = ch & 7;
            const uint32_t so = (uint32_t)(r * PSTRH + c * 8) * 2;
            cp_async16(abase + so, Ap + (size_t)r * Dc + k0 + c * 8);
            cp_async16(bbase + so, Wp + (size_t)r * Dc + k0 + c * 8);
        }
        cp_commit();
    };

    float acc[2][8][4] = {};

    load_tiles(0, 0);
    const int NKB = Dc / PBKH;  // 16
    for (int kb = 0; kb < NKB; kb++) {
        const int buf = kb & 1;
        if (kb + 1 < NKB) {
            load_tiles(kb + 1, buf ^ 1);
            cp_wait<1>();
        } else {
            cp_wait<0>();
        }
        __syncthreads();

        const uint32_t* au = reinterpret_cast<const uint32_t*>(sm + buf * 2 * PTILEH);
        const uint32_t* bu = au + PTILEH / 2;
#pragma unroll
        for (int ks = 0; ks < 4; ks++) {
            const int w = ks * 8 + t4;  // word index within row
            uint32_t af[2][4];
#pragma unroll
            for (int mt = 0; mt < 2; mt++) {
                const int r = wm * 32 + mt * 16 + g;
                af[mt][0] = au[r * 36 + w];
                af[mt][1] = au[(r + 8) * 36 + w];
                af[mt][2] = au[r * 36 + w + 4];
                af[mt][3] = au[(r + 8) * 36 + w + 4];
            }
#pragma unroll
            for (int nt = 0; nt < 8; nt++) {
                const int n = wn * 64 + nt * 8 + g;
                uint32_t bf[2];
                bf[0] = bu[n * 36 + w];
                bf[1] = bu[n * 36 + w + 4];
#pragma unroll
                for (int mt = 0; mt < 2; mt++) mma_f16(acc[mt][nt], af[mt], bf);
            }
        }
        __syncthreads();
    }

    // Epilogue
#pragma unroll
    for (int mt = 0; mt < 2; mt++) {
#pragma unroll
        for (int half_ = 0; half_ < 2; half_++) {
            const int m = row0 + wm * 32 + mt * 16 + g + half_ * 8;
            const int b = m >> 11;
            const int s = m & 2047;
#pragma unroll
            for (int nt = 0; nt < 8; nt++) {
                const int n = col0 + wn * 64 + nt * 8 + t4 * 2;
                const float ox = acc[mt][nt][half_ * 2 + 0] + bias[n];
                const float oy = acc[mt][nt][half_ * 2 + 1] + bias[n + 1];
                if (MODE == 0) {
                    float2 o = {ox, oy};
                    *reinterpret_cast<float2*>((float*)outp + (size_t)m * Dc + n) = o;
                } else if (MODE == 1) {
                    const int h = n >> 6, dk = n & 63;
                    __half2 o = __floats2half2_rn(ox, oy);
                    *reinterpret_cast<__half2*>(
                        (__half*)outp + ((size_t)((b * Hc + h) * Sc + s) << 6) + dk) = o;
                } else {
                    const int h = n >> 6, dk = n & 63;
                    __half* dst = (__half*)outp +
                                  ((size_t)((b * Hc + h) * DKc + dk)) * Sc + s;
                    dst[0] = __float2half_rn(ox);
                    dst[Sc] = __float2half_rn(oy);
                }
            }
        }
    }
}

// Merged Q/K/V projection: blockIdx.z selects projection.
__global__ void __launch_bounds__(256) proj_qkv_kernel(
    const float* __restrict__ bq, const float* __restrict__ bk,
    const float* __restrict__ bv) {
    extern __shared__ __half smh[];
    const int z = blockIdx.z;
    const int row0 = blockIdx.y * 128, col0 = blockIdx.x * 128;
    if (z == 0) {
        proj_body<1>(g_q16, g_Wq16, bq, g_Qh, smh, row0, col0);
    } else if (z == 1) {
        proj_body<1>(g_k16, g_Wk16, bk, g_Kh, smh, row0, col0);
    } else {
        proj_body<2>(g_v16, g_Wv16, bv, g_Vt, smh, row0, col0);
    }
}

__global__ void __launch_bounds__(256) proj_o_kernel(const float* __restrict__ bo,
                                                     float* __restrict__ out) {
    extern __shared__ __half smh[];
    proj_body<0>(g_att, g_Wo16, bo, out, smh, blockIdx.y * 128, blockIdx.x * 128);
}

// ---------------------------------------------------------------------------
// Flash attention (causal), fp16 mma, row-owning warps, double-buffered K/V.
// CTA: 128 q-rows x 64-key tiles, 8 warps x 16 rows.
// ---------------------------------------------------------------------------
constexpr int AT = 72;  // half stride (36 words) -> banks 4g+t4 conflict-free
constexpr int KV_TILE = 64 * AT;  // halfs
// smem: Ks[2][64][AT], Vt[2][64][AT], Pall[128][AT]
constexpr int ATTN_SMEM_HALFS = 2 * KV_TILE + 2 * KV_TILE + 128 * AT;
constexpr int ATTN_SMEM_BYTES = ATTN_SMEM_HALFS * 2;  // 55296

__global__ void __launch_bounds__(256, 2) attn_kernel(float* /*unused*/) {
    extern __shared__ __half smh[];
    __half* KsB = smh;                    // 2 x [64][AT]
    __half* VtB = KsB + 2 * KV_TILE;      // 2 x [64][AT]
    __half* Pall = VtB + 2 * KV_TILE;     // [128][AT]: Q staging then P

    const int tid = threadIdx.x;
    const int wid = tid >> 5;
    const int lid = tid & 31;
    const int g = lid >> 2;
    const int t4 = lid & 3;
    const int qt = blockIdx.x;
    const int bh = blockIdx.y;
    const int rb = wid * 16;

    const __half* Qg = g_Qh + ((size_t)bh * Sc + qt * 128) * DKc;
    const __half* Kg = g_Kh + (size_t)bh * Sc * DKc;
    const __half* Vg = g_Vt + (size_t)bh * DKc * Sc;

    const uint32_t smb = smem_u32(smh);
    const uint32_t ksb = smb;
    const uint32_t vtb = smb + 2 * KV_TILE * 2;
    const uint32_t pab = smb + 4 * KV_TILE * 2;

    // K/V tile loader (cp.async): 512 chunks of 16B each per tile, 2/thread
    auto load_kv = [&](int kt, int buf) {
#pragma unroll
        for (int i = 0; i < 2; i++) {
            const int ch = tid + i * 256;
            const int r = ch >> 3;
            const int c = ch & 7;
            const uint32_t so = (uint32_t)(buf * KV_TILE + r * AT + c * 8) * 2;
            cp_async16(ksb + so, Kg + ((size_t)(kt * 64 + r)) * DKc + c * 8);
            cp_async16(vtb + so, Vg + (size_t)r * Sc + kt * 64 + c * 8);
        }
        cp_commit();
    };

    // Stage Q (cp.async): 1024 chunks, 4/thread
    {
#pragma unroll
        for (int i = 0; i < 4; i++) {
            const int ch = tid + i * 256;
            const int r = ch >> 3;
            const int c = ch & 7;
            cp_async16(pab + (uint32_t)(r * AT + c * 8) * 2,
                       Qg + (size_t)r * DKc + c * 8);
        }
        cp_commit();
    }
    load_kv(0, 0);      // group: KV0
    cp_wait<1>();       // Q done
    __syncthreads();

    // Q fragments (pre-scaled by 1/8 applied to S after MMA instead: cheaper to
    // scale here via accumulate? Keep Q raw; scale S by 0.125 in mask step.)
    uint32_t qf[4][4];
    {
        const uint32_t* pu = reinterpret_cast<const uint32_t*>(Pall);
#pragma unroll
        for (int ks = 0; ks < 4; ks++) {
            const int w = ks * 8 + t4;
            qf[ks][0] = pu[(rb + g) * 36 + w];
            qf[ks][1] = pu[(rb + g + 8) * 36 + w];
            qf[ks][2] = pu[(rb + g) * 36 + w + 4];
            qf[ks][3] = pu[(rb + g + 8) * 36 + w + 4];
        }
    }

    __half* Pw = Pall + rb * AT;  // warp-private P rows
    uint32_t* Pwu = reinterpret_cast<uint32_t*>(Pw);

    float m0 = -1e30f, m1 = -1e30f, l0 = 0.0f, l1 = 0.0f;
    float Oacc[8][4] = {};
    const float scale = 0.125f;

    const int ktmax = 2 * qt + 1;
    for (int kt = 0; kt <= ktmax; ++kt) {
        __syncthreads();  // all warps done with buf[(kt+1)&1] (iter kt-1) + qf read
        if (kt < ktmax) {
            load_kv(kt + 1, (kt + 1) & 1);
            cp_wait<1>();
        } else {
            cp_wait<0>();
        }
        __syncthreads();  // buf[kt&1] visible

        const int buf = kt & 1;
        const uint32_t* Ku = reinterpret_cast<const uint32_t*>(KsB + buf * KV_TILE);
        const uint32_t* Vu = reinterpret_cast<const uint32_t*>(VtB + buf * KV_TILE);

        // S = Q @ K^T : 16 rows x 64 keys, k-dim 64 (4 k16-steps)
        float sacc[8][4] = {};
#pragma unroll
        for (int ks = 0; ks < 4; ks++) {
            const int w = ks * 8 + t4;
#pragma unroll
            for (int nt = 0; nt < 8; nt++) {
                const int n = nt * 8 + g;
                uint32_t bf[2];
                bf[0] = Ku[n * 36 + w];
                bf[1] = Ku[n * 36 + w + 4];
                mma_f16(sacc[nt], qf[ks], bf);
            }
        }

        // scale + causal mask
#pragma unroll
        for (int nt = 0; nt < 8; nt++) {
            sacc[nt][0] *= scale;
            sacc[nt][1] *= scale;
            sacc[nt][2] *= scale;
            sacc[nt][3] *= scale;
        }
        if (kt >= 2 * qt) {
            const int cb = kt * 64;
            const int r0g = qt * 128 + rb + g;
            const int r1g = r0g + 8;
#pragma unroll
            for (int nt = 0; nt < 8; nt++) {
                const int c0 = cb + nt * 8 + 2 * t4;
                if (c0 > r0g)     sacc[nt][0] = -1e30f;
                if (c0 + 1 > r0g) sacc[nt][1] = -1e30f;
                if (c0 > r1g)     sacc[nt][2] = -1e30f;
                if (c0 + 1 > r1g) sacc[nt][3] = -1e30f;
            }
        }

        // row max
        float pm0 = -1e30f, pm1 = -1e30f;
#pragma unroll
        for (int nt = 0; nt < 8; nt++) {
            pm0 = fmaxf(pm0, fmaxf(sacc[nt][0], sacc[nt][1]));
            pm1 = fmaxf(pm1, fmaxf(sacc[nt][2], sacc[nt][3]));
        }
        pm0 = fmaxf(pm0, __shfl_xor_sync(0xffffffffu, pm0, 1));
        pm0 = fmaxf(pm0, __shfl_xor_sync(0xffffffffu, pm0, 2));
        pm1 = fmaxf(pm1, __shfl_xor_sync(0xffffffffu, pm1, 1));
        pm1 = fmaxf(pm1, __shfl_xor_sync(0xffffffffu, pm1, 2));

        const float mn0 = fmaxf(m0, pm0);
        const float mn1 = fmaxf(m1, pm1);
        const float a0 = __expf(m0 - mn0);
        const float a1 = __expf(m1 - mn1);
        m0 = mn0;
        m1 = mn1;

        // exp, P write (half2), partial sums
        float ps0 = 0.0f, ps1 = 0.0f;
#pragma unroll
        for (int nt = 0; nt < 8; nt++) {
            const float p0 = __expf(sacc[nt][0] - mn0);
            const float p1 = __expf(sacc[nt][1] - mn0);
            const float p2 = __expf(sacc[nt][2] - mn1);
            const float p3 = __expf(sacc[nt][3] - mn1);
            ps0 += p0 + p1;
            ps1 += p2 + p3;
            Pwu[g * 36 + 4 * nt + t4] = pack_h2(p0, p1);
            Pwu[(g + 8) * 36 + 4 * nt + t4] = pack_h2(p2, p3);
        }
        ps0 += __shfl_xor_sync(0xffffffffu, ps0, 1);
        ps0 += __shfl_xor_sync(0xffffffffu, ps0, 2);
        ps1 += __shfl_xor_sync(0xffffffffu, ps1, 1);
        ps1 += __shfl_xor_sync(0xffffffffu, ps1, 2);
        l0 = l0 * a0 + ps0;
        l1 = l1 * a1 + ps1;

#pragma unroll
        for (int nt = 0; nt < 8; nt++) {
            Oacc[nt][0] *= a0;
            Oacc[nt][1] *= a0;
            Oacc[nt][2] *= a1;
            Oacc[nt][3] *= a1;
        }
        __syncwarp();

        // O += P @ V
#pragma unroll
        for (int ks = 0; ks < 4; ks++) {
            const int w = ks * 8 + t4;
            uint32_t af[4];
            af[0] = Pwu[g * 36 + w];
            af[1] = Pwu[(g + 8) * 36 + w];
            af[2] = Pwu[g * 36 + w + 4];
            af[3] = Pwu[(g + 8) * 36 + w + 4];
#pragma unroll
            for (int nt = 0; nt < 8; nt++) {
                const int n = nt * 8 + g;
                uint32_t bf[2];
                bf[0] = Vu[n * 36 + w];
                bf[1] = Vu[n * 36 + w + 4];
                mma_f16(Oacc[nt], af, bf);
            }
        }
        __syncwarp();
    }

    // Epilogue: normalize, write g_att (half, [b,s,d])
    const int b = bh >> 4;
    const int h = bh & 15;
    const float inv0 = 1.0f / l0;
    const float inv1 = 1.0f / l1;
    const int s0 = qt * 128 + rb + g;
    const int s1 = s0 + 8;
#pragma unroll
    for (int nt = 0; nt < 8; nt++) {
        const int c = nt * 8 + 2 * t4;
        __half2 o0 = __floats2half2_rn(Oacc[nt][0] * inv0, Oacc[nt][1] * inv0);
        __half2 o1 = __floats2half2_rn(Oacc[nt][2] * inv1, Oacc[nt][3] * inv1);
        *reinterpret_cast<__half2*>(g_att + ((size_t)(b * Sc + s0)) * Dc + h * 64 + c) = o0;
        *reinterpret_cast<__half2*>(g_att + ((size_t)(b * Sc + s1)) * Dc + h * 64 + c) = o1;
    }
}

// ---------------------------------------------------------------------------
extern "C" void kernel_launch(void* const* d_in, const int* in_sizes, int n_in,
                              void* d_out, int out_size) {
    const float* q  = (const float*)d_in[0];
    const float* k  = (const float*)d_in[1];
    const float* v  = (const float*)d_in[2];
    // d_in[3] = mask (causal implemented directly)
    const float* Wq = (const float*)d_in[4];
    const float* bq = (const float*)d_in[5];
    const float* Wk = (const float*)d_in[6];
    const float* bk = (const float*)d_in[7];
    const float* Wv = (const float*)d_in[8];
    const float* bv = (const float*)d_in[9];
    const float* Wo = (const float*)d_in[10];
    const float* bo = (const float*)d_in[11];
    float* out = (float*)d_out;

    cudaFuncSetAttribute(proj_qkv_kernel,
                         cudaFuncAttributeMaxDynamicSharedMemorySize, PROJ_SMEM);
    cudaFuncSetAttribute(proj_o_kernel,
                         cudaFuncAttributeMaxDynamicSharedMemorySize, PROJ_SMEM);
    cudaFuncSetAttribute(attn_kernel,
                         cudaFuncAttributeMaxDynamicSharedMemorySize, ATTN_SMEM_BYTES);

    cvt_kernel<<<2048, 256>>>(q, k, v, Wq, Wk, Wv, Wo);

    dim3 qkvgrid(Dc / 128, Mc / 128, 3);  // (8, 32, 3)
    proj_qkv_kernel<<<qkvgrid, 256, PROJ_SMEM>>>(bq, bk, bv);

    dim3 agrid(Sc / 128, Bc * Hc);        // (16, 32)
    attn_kernel<<<agrid, 256, ATTN_SMEM_BYTES>>>(out);

    dim3 ogrid(Dc / 128, Mc / 128);       // (8, 32)
    proj_o_kernel<<<ogrid, 256, PROJ_SMEM>>>(bo, out);
}

// round 13
// speedup vs baseline: 12.5069x; 1.0839x over previous
#include <cuda_runtime.h>
#include <cuda_fp16.h>
#include <cstdint>

// Problem constants
constexpr int Bc = 2;
constexpr int Sc = 2048;
constexpr int Dc = 1024;
constexpr int Hc = 16;
constexpr int DKc = 64;
constexpr int Mc = Bc * Sc;  // 4096

// Half scratch (device globals: allocation-free)
__device__ __half g_q16[(size_t)Mc * Dc];
__device__ __half g_k16[(size_t)Mc * Dc];
__device__ __half g_v16[(size_t)Mc * Dc];
__device__ __half g_Wq16[(size_t)Dc * Dc];
__device__ __half g_Wk16[(size_t)Dc * Dc];
__device__ __half g_Wv16[(size_t)Dc * Dc];
__device__ __half g_Wo16[(size_t)Dc * Dc];
__device__ __half g_Qh[(size_t)Bc * Hc * Sc * DKc];   // [b,h,s,dk]
__device__ __half g_Kh[(size_t)Bc * Hc * Sc * DKc];   // [b,h,s,dk]
__device__ __half g_Vt[(size_t)Bc * Hc * DKc * Sc];   // [b,h,dk,s] (transposed)
__device__ __half g_att[(size_t)Mc * Dc];             // [b,s,d]

// ---------------------------------------------------------------------------
// Helpers
// ---------------------------------------------------------------------------
__device__ __forceinline__ uint32_t smem_u32(const void* p) {
    uint32_t a;
    asm("{ .reg .u64 t; cvta.to.shared.u64 t, %1; cvt.u32.u64 %0, t; }"
        : "=r"(a) : "l"(p));
    return a;
}
__device__ __forceinline__ void cp_async16(uint32_t s, const void* g) {
    asm volatile("cp.async.cg.shared.global [%0], [%1], 16;" :: "r"(s), "l"(g));
}
__device__ __forceinline__ void cp_commit() {
    asm volatile("cp.async.commit_group;" ::: "memory");
}
template <int N>
__device__ __forceinline__ void cp_wait() {
    asm volatile("cp.async.wait_group %0;" :: "n"(N) : "memory");
}
__device__ __forceinline__ uint32_t pack_h2(float a, float b) {
    __half2 h = __floats2half2_rn(a, b);
    return *reinterpret_cast<uint32_t*>(&h);
}
__device__ __forceinline__ void mma_f16(float* C, const uint32_t* A,
                                        const uint32_t* B) {
    asm volatile(
        "mma.sync.aligned.m16n8k16.row.col.f32.f16.f16.f32 "
        "{%0,%1,%2,%3}, {%4,%5,%6,%7}, {%8,%9}, {%0,%1,%2,%3};"
        : "+f"(C[0]), "+f"(C[1]), "+f"(C[2]), "+f"(C[3])
        : "r"(A[0]), "r"(A[1]), "r"(A[2]), "r"(A[3]), "r"(B[0]), "r"(B[1]));
}
__device__ __forceinline__ void ldm_x4(uint32_t& r0, uint32_t& r1, uint32_t& r2,
                                       uint32_t& r3, uint32_t addr) {
    asm volatile("ldmatrix.sync.aligned.m8n8.x4.shared.b16 {%0,%1,%2,%3}, [%4];"
                 : "=r"(r0), "=r"(r1), "=r"(r2), "=r"(r3) : "r"(addr));
}

// ---------------------------------------------------------------------------
// Prepass: fp32 -> fp16 conversion of inputs + weights.
// ---------------------------------------------------------------------------
__global__ void __launch_bounds__(256) cvt_kernel(const float* __restrict__ q,
                                                  const float* __restrict__ k,
                                                  const float* __restrict__ v,
                                                  const float* __restrict__ Wq,
                                                  const float* __restrict__ Wk,
                                                  const float* __restrict__ Wv,
                                                  const float* __restrict__ Wo) {
    constexpr size_t NIN = 1048576;   // float4 per input
    constexpr size_t NW = 262144;     // float4 per weight
    const size_t total = 3 * NIN + 4 * NW;
    for (size_t idx = blockIdx.x * 256 + threadIdx.x; idx < total;
         idx += (size_t)gridDim.x * 256) {
        const float* src;
        __half* dst;
        size_t off;
        if (idx < 3 * NIN) {
            const int w = (int)(idx / NIN);
            off = idx % NIN;
            src = (w == 0) ? q : (w == 1) ? k : v;
            dst = (w == 0) ? g_q16 : (w == 1) ? g_k16 : g_v16;
        } else {
            const size_t r = idx - 3 * NIN;
            const int w = (int)(r / NW);
            off = r % NW;
            src = (w == 0) ? Wq : (w == 1) ? Wk : (w == 2) ? Wv : Wo;
            dst = (w == 0) ? g_Wq16 : (w == 1) ? g_Wk16 : (w == 2) ? g_Wv16 : g_Wo16;
        }
        float4 f = reinterpret_cast<const float4*>(src)[off];
        uint2 u;
        u.x = pack_h2(f.x, f.y);
        u.y = pack_h2(f.z, f.w);
        reinterpret_cast<uint2*>(dst)[off] = u;
    }
}

// ---------------------------------------------------------------------------
// fp16 projection GEMM with ldmatrix fragments.
// CTA 128x128, BK=64 halfs, double-buffered cp.async, 8 warps (4m x 2n).
// MODE 0: fp32 row-major out + bias; MODE 1: half [b,h,s,dk]; MODE 2: half
// [b,h,dk,s] (V transposed).
// ---------------------------------------------------------------------------
constexpr int PBKH = 64;
constexpr int PSTRH = 72;
constexpr int PTILEH = 128 * PSTRH;
constexpr int PROJ_SMEM = 4 * PTILEH * 2;  // 73728 B

template <int MODE>
__device__ __forceinline__ void proj_body(const __half* __restrict__ A,
                                          const __half* __restrict__ W,
                                          const float* __restrict__ bias,
                                          void* __restrict__ outp,
                                          __half* sm, int row0, int col0) {
    const uint32_t smb = smem_u32(sm);
    const int tid = threadIdx.x;
    const int wid = tid >> 5;
    const int lid = tid & 31;
    const int g = lid >> 2;
    const int t4 = lid & 3;
    const int wm = wid & 3;
    const int wn = wid >> 2;
    const int qq = lid >> 3;   // ldmatrix lane-quad 0..3
    const int rr = lid & 7;    // row within 8

    // ldmatrix lane offsets (bytes, within tile)
    const uint32_t aoff =
        (uint32_t)((wm * 32 + (qq & 1) * 8 + rr) * PSTRH + (qq >> 1) * 8) * 2;
    const uint32_t boff =
        (uint32_t)((wn * 64 + (qq >> 1) * 8 + rr) * PSTRH + (qq & 1) * 8) * 2;

    const __half* Ap = A + (size_t)row0 * Dc;
    const __half* Wp = W + (size_t)col0 * Dc;

    auto load_tiles = [&](int kb, int buf) {
        const int k0 = kb * PBKH;
        const uint32_t abase = smb + (uint32_t)(buf * 2 * PTILEH) * 2;
        const uint32_t bbase = abase + (uint32_t)PTILEH * 2;
#pragma unroll
        for (int i = 0; i < 4; i++) {
            const int ch = tid + i * 256;
            const int r = ch >> 3;
            const int c = ch & 7;
            const uint32_t so = (uint32_t)(r * PSTRH + c * 8) * 2;
            cp_async16(abase + so, Ap + (size_t)r * Dc + k0 + c * 8);
            cp_async16(bbase + so, Wp + (size_t)r * Dc + k0 + c * 8);
        }
        cp_commit();
    };

    float acc[2][8][4] = {};

    load_tiles(0, 0);
    const int NKB = Dc / PBKH;  // 16
    for (int kb = 0; kb < NKB; kb++) {
        const int buf = kb & 1;
        if (kb + 1 < NKB) {
            load_tiles(kb + 1, buf ^ 1);
            cp_wait<1>();
        } else {
            cp_wait<0>();
        }
        __syncthreads();

        const uint32_t abase = smb + (uint32_t)(buf * 2 * PTILEH) * 2;
        const uint32_t bbase = abase + (uint32_t)PTILEH * 2;
#pragma unroll
        for (int ks = 0; ks < 4; ks++) {
            uint32_t af[2][4];
            ldm_x4(af[0][0], af[0][1], af[0][2], af[0][3],
                   abase + aoff + ks * 32);
            ldm_x4(af[1][0], af[1][1], af[1][2], af[1][3],
                   abase + aoff + 16 * PSTRH * 2 + ks * 32);
            uint32_t bf[8][2];
#pragma unroll
            for (int p = 0; p < 4; p++) {
                ldm_x4(bf[2 * p][0], bf[2 * p][1], bf[2 * p + 1][0],
                       bf[2 * p + 1][1],
                       bbase + boff + (uint32_t)(p * 16 * PSTRH) * 2 + ks * 32);
            }
#pragma unroll
            for (int nt = 0; nt < 8; nt++)
#pragma unroll
                for (int mt = 0; mt < 2; mt++) mma_f16(acc[mt][nt], af[mt], bf[nt]);
        }
        __syncthreads();
    }

    // Epilogue
#pragma unroll
    for (int mt = 0; mt < 2; mt++) {
#pragma unroll
        for (int half_ = 0; half_ < 2; half_++) {
            const int m = row0 + wm * 32 + mt * 16 + g + half_ * 8;
            const int b = m >> 11;
            const int s = m & 2047;
#pragma unroll
            for (int nt = 0; nt < 8; nt++) {
                const int n = col0 + wn * 64 + nt * 8 + t4 * 2;
                const float ox = acc[mt][nt][half_ * 2 + 0] + bias[n];
                const float oy = acc[mt][nt][half_ * 2 + 1] + bias[n + 1];
                if (MODE == 0) {
                    float2 o = {ox, oy};
                    *reinterpret_cast<float2*>((float*)outp + (size_t)m * Dc + n) = o;
                } else if (MODE == 1) {
                    const int h = n >> 6, dk = n & 63;
                    __half2 o = __floats2half2_rn(ox, oy);
                    *reinterpret_cast<__half2*>(
                        (__half*)outp + ((size_t)((b * Hc + h) * Sc + s) << 6) + dk) = o;
                } else {
                    const int h = n >> 6, dk = n & 63;
                    __half* dst = (__half*)outp +
                                  ((size_t)((b * Hc + h) * DKc + dk)) * Sc + s;
                    dst[0] = __float2half_rn(ox);
                    dst[Sc] = __float2half_rn(oy);
                }
            }
        }
    }
}

__global__ void __launch_bounds__(256) proj_qkv_kernel(
    const float* __restrict__ bq, const float* __restrict__ bk,
    const float* __restrict__ bv) {
    extern __shared__ __half smh[];
    const int z = blockIdx.z;
    const int row0 = blockIdx.y * 128, col0 = blockIdx.x * 128;
    if (z == 0) {
        proj_body<1>(g_q16, g_Wq16, bq, g_Qh, smh, row0, col0);
    } else if (z == 1) {
        proj_body<1>(g_k16, g_Wk16, bk, g_Kh, smh, row0, col0);
    } else {
        proj_body<2>(g_v16, g_Wv16, bv, g_Vt, smh, row0, col0);
    }
}

__global__ void __launch_bounds__(256) proj_o_kernel(const float* __restrict__ bo,
                                                     float* __restrict__ out) {
    extern __shared__ __half smh[];
    proj_body<0>(g_att, g_Wo16, bo, out, smh, blockIdx.y * 128, blockIdx.x * 128);
}

// ---------------------------------------------------------------------------
// Flash attention (causal), fp16 mma + ldmatrix, row-owning warps,
// double-buffered K/V. CTA: 128 q-rows x 64-key tiles, 8 warps x 16 rows.
// ---------------------------------------------------------------------------
constexpr int AT = 72;            // half stride (36 words)
constexpr int KV_TILE = 64 * AT;  // halfs
constexpr int ATTN_SMEM_HALFS = 2 * KV_TILE + 2 * KV_TILE + 128 * AT;
constexpr int ATTN_SMEM_BYTES = ATTN_SMEM_HALFS * 2;  // 55296

__global__ void __launch_bounds__(256, 2) attn_kernel(float* /*unused*/) {
    extern __shared__ __half smh[];

    const int tid = threadIdx.x;
    const int wid = tid >> 5;
    const int lid = tid & 31;
    const int g = lid >> 2;
    const int t4 = lid & 3;
    const int qq = lid >> 3;
    const int rr = lid & 7;
    const int qt = blockIdx.x;
    const int bh = blockIdx.y;
    const int rb = wid * 16;

    const __half* Qg = g_Qh + ((size_t)bh * Sc + qt * 128) * DKc;
    const __half* Kg = g_Kh + (size_t)bh * Sc * DKc;
    const __half* Vg = g_Vt + (size_t)bh * DKc * Sc;

    const uint32_t smb = smem_u32(smh);
    const uint32_t ksb = smb;
    const uint32_t vtb = smb + 2 * KV_TILE * 2;
    const uint32_t pab = smb + 4 * KV_TILE * 2;
    __half* Pall = smh + 4 * KV_TILE;     // [128][AT]: Q staging then P

    // ldmatrix lane offsets (bytes)
    const uint32_t a_off =
        (uint32_t)(((qq & 1) * 8 + rr) * AT + (qq >> 1) * 8) * 2;  // A-style 16-row
    const uint32_t b_off =
        (uint32_t)(((qq >> 1) * 8 + rr) * AT + (qq & 1) * 8) * 2;  // B-style 16-row

    auto load_kv = [&](int kt, int buf) {
#pragma unroll
        for (int i = 0; i < 2; i++) {
            const int ch = tid + i * 256;
            const int r = ch >> 3;
            const int c = ch & 7;
            const uint32_t so = (uint32_t)(buf * KV_TILE + r * AT + c * 8) * 2;
            cp_async16(ksb + so, Kg + ((size_t)(kt * 64 + r)) * DKc + c * 8);
            cp_async16(vtb + so, Vg + (size_t)r * Sc + kt * 64 + c * 8);
        }
        cp_commit();
    };

    // Stage Q
    {
#pragma unroll
        for (int i = 0; i < 4; i++) {
            const int ch = tid + i * 256;
            const int r = ch >> 3;
            const int c = ch & 7;
            cp_async16(pab + (uint32_t)(r * AT + c * 8) * 2,
                       Qg + (size_t)r * DKc + c * 8);
        }
        cp_commit();
    }
    load_kv(0, 0);
    cp_wait<1>();  // Q staged
    __syncthreads();

    // Q fragments via ldmatrix (4 x4 ops)
    uint32_t qf[4][4];
    {
        const uint32_t qbase = pab + (uint32_t)(rb * AT) * 2;
#pragma unroll
        for (int ks = 0; ks < 4; ks++)
            ldm_x4(qf[ks][0], qf[ks][1], qf[ks][2], qf[ks][3],
                   qbase + a_off + ks * 32);
    }

    __half* Pw = Pall + rb * AT;
    uint32_t* Pwu = reinterpret_cast<uint32_t*>(Pw);
    const uint32_t pwbase = pab + (uint32_t)(rb * AT) * 2;

    float m0 = -1e30f, m1 = -1e30f, l0 = 0.0f, l1 = 0.0f;
    float Oacc[8][4] = {};
    const float scale = 0.125f;

    const int ktmax = 2 * qt + 1;
    for (int kt = 0; kt <= ktmax; ++kt) {
        __syncthreads();
        if (kt < ktmax) {
            load_kv(kt + 1, (kt + 1) & 1);
            cp_wait<1>();
        } else {
            cp_wait<0>();
        }
        __syncthreads();

        const int buf = kt & 1;
        const uint32_t kbase = ksb + (uint32_t)(buf * KV_TILE) * 2;
        const uint32_t vbase = vtb + (uint32_t)(buf * KV_TILE) * 2;

        // S = Q @ K^T
        float sacc[8][4] = {};
#pragma unroll
        for (int ks = 0; ks < 4; ks++) {
            uint32_t bf[8][2];
#pragma unroll
            for (int p = 0; p < 4; p++) {
                ldm_x4(bf[2 * p][0], bf[2 * p][1], bf[2 * p + 1][0],
                       bf[2 * p + 1][1],
                       kbase + b_off + (uint32_t)(p * 16 * AT) * 2 + ks * 32);
            }
#pragma unroll
            for (int nt = 0; nt < 8; nt++) mma_f16(sacc[nt], qf[ks], bf[nt]);
        }

        // scale + causal mask
#pragma unroll
        for (int nt = 0; nt < 8; nt++) {
            sacc[nt][0] *= scale;
            sacc[nt][1] *= scale;
            sacc[nt][2] *= scale;
            sacc[nt][3] *= scale;
        }
        if (kt >= 2 * qt) {
            const int cb = kt * 64;
            const int r0g = qt * 128 + rb + g;
            const int r1g = r0g + 8;
#pragma unroll
            for (int nt = 0; nt < 8; nt++) {
                const int c0 = cb + nt * 8 + 2 * t4;
                if (c0 > r0g)     sacc[nt][0] = -1e30f;
                if (c0 + 1 > r0g) sacc[nt][1] = -1e30f;
                if (c0 > r1g)     sacc[nt][2] = -1e30f;
                if (c0 + 1 > r1g) sacc[nt][3] = -1e30f;
            }
        }

        // row max
        float pm0 = -1e30f, pm1 = -1e30f;
#pragma unroll
        for (int nt = 0; nt < 8; nt++) {
            pm0 = fmaxf(pm0, fmaxf(sacc[nt][0], sacc[nt][1]));
            pm1 = fmaxf(pm1, fmaxf(sacc[nt][2], sacc[nt][3]));
        }
        pm0 = fmaxf(pm0, __shfl_xor_sync(0xffffffffu, pm0, 1));
        pm0 = fmaxf(pm0, __shfl_xor_sync(0xffffffffu, pm0, 2));
        pm1 = fmaxf(pm1, __shfl_xor_sync(0xffffffffu, pm1, 1));
        pm1 = fmaxf(pm1, __shfl_xor_sync(0xffffffffu, pm1, 2));

        const float mn0 = fmaxf(m0, pm0);
        const float mn1 = fmaxf(m1, pm1);
        const float a0 = __expf(m0 - mn0);
        const float a1 = __expf(m1 - mn1);
        m0 = mn0;
        m1 = mn1;

        // exp, P write, partial sums
        float ps0 = 0.0f, ps1 = 0.0f;
#pragma unroll
        for (int nt = 0; nt < 8; nt++) {
            const float p0 = __expf(sacc[nt][0] - mn0);
            const float p1 = __expf(sacc[nt][1] - mn0);
            const float p2 = __expf(sacc[nt][2] - mn1);
            const float p3 = __expf(sacc[nt][3] - mn1);
            ps0 += p0 + p1;
            ps1 += p2 + p3;
            Pwu[g * 36 + 4 * nt + t4] = pack_h2(p0, p1);
            Pwu[(g + 8) * 36 + 4 * nt + t4] = pack_h2(p2, p3);
        }
        ps0 += __shfl_xor_sync(0xffffffffu, ps0, 1);
        ps0 += __shfl_xor_sync(0xffffffffu, ps0, 2);
        ps1 += __shfl_xor_sync(0xffffffffu, ps1, 1);
        ps1 += __shfl_xor_sync(0xffffffffu, ps1, 2);
        l0 = l0 * a0 + ps0;
        l1 = l1 * a1 + ps1;

#pragma unroll
        for (int nt = 0; nt < 8; nt++) {
            Oacc[nt][0] *= a0;
            Oacc[nt][1] *= a0;
            Oacc[nt][2] *= a1;
            Oacc[nt][3] *= a1;
        }
        __syncwarp();

        // O += P @ V
#pragma unroll
        for (int ks = 0; ks < 4; ks++) {
            uint32_t af[4];
            ldm_x4(af[0], af[1], af[2], af[3], pwbase + a_off + ks * 32);
            uint32_t bf[8][2];
#pragma unroll
            for (int p = 0; p < 4; p++) {
                ldm_x4(bf[2 * p][0], bf[2 * p][1], bf[2 * p + 1][0],
                       bf[2 * p + 1][1],
                       vbase + b_off + (uint32_t)(p * 16 * AT) * 2 + ks * 32);
            }
#pragma unroll
            for (int nt = 0; nt < 8; nt++) mma_f16(Oacc[nt], af, bf[nt]);
        }
        __syncwarp();
    }

    // Epilogue
    const int b = bh >> 4;
    const int h = bh & 15;
    const float inv0 = 1.0f / l0;
    const float inv1 = 1.0f / l1;
    const int s0 = qt * 128 + rb + g;
    const int s1 = s0 + 8;
#pragma unroll
    for (int nt = 0; nt < 8; nt++) {
        const int c = nt * 8 + 2 * t4;
        __half2 o0 = __floats2half2_rn(Oacc[nt][0] * inv0, Oacc[nt][1] * inv0);
        __half2 o1 = __floats2half2_rn(Oacc[nt][2] * inv1, Oacc[nt][3] * inv1);
        *reinterpret_cast<__half2*>(g_att + ((size_t)(b * Sc + s0)) * Dc + h * 64 + c) = o0;
        *reinterpret_cast<__half2*>(g_att + ((size_t)(b * Sc + s1)) * Dc + h * 64 + c) = o1;
    }
}

// ---------------------------------------------------------------------------
extern "C" void kernel_launch(void* const* d_in, const int* in_sizes, int n_in,
                              void* d_out, int out_size) {
    const float* q  = (const float*)d_in[0];
    const float* k  = (const float*)d_in[1];
    const float* v  = (const float*)d_in[2];
    // d_in[3] = mask (causal implemented directly)
    const float* Wq = (const float*)d_in[4];
    const float* bq = (const float*)d_in[5];
    const float* Wk = (const float*)d_in[6];
    const float* bk = (const float*)d_in[7];
    const float* Wv = (const float*)d_in[8];
    const float* bv = (const float*)d_in[9];
    const float* Wo = (const float*)d_in[10];
    const float* bo = (const float*)d_in[11];
    float* out = (float*)d_out;

    cudaFuncSetAttribute(proj_qkv_kernel,
                         cudaFuncAttributeMaxDynamicSharedMemorySize, PROJ_SMEM);
    cudaFuncSetAttribute(proj_o_kernel,
                         cudaFuncAttributeMaxDynamicSharedMemorySize, PROJ_SMEM);
    cudaFuncSetAttribute(attn_kernel,
                         cudaFuncAttributeMaxDynamicSharedMemorySize, ATTN_SMEM_BYTES);

    cvt_kernel<<<2048, 256>>>(q, k, v, Wq, Wk, Wv, Wo);

    dim3 qkvgrid(Dc / 128, Mc / 128, 3);  // (8, 32, 3)
    proj_qkv_kernel<<<qkvgrid, 256, PROJ_SMEM>>>(bq, bk, bv);

    dim3 agrid(Sc / 128, Bc * Hc);        // (16, 32)
    attn_kernel<<<agrid, 256, ATTN_SMEM_BYTES>>>(out);

    dim3 ogrid(Dc / 128, Mc / 128);       // (8, 32)
    proj_o_kernel<<<ogrid, 256, PROJ_SMEM>>>(bo, out);
}